// round 7
// baseline (speedup 1.0000x reference)
#include <cuda_runtime.h>
#include <math.h>

#define BB 8
#define CC 128
#define C2 256
#define NN 32768
#define KS 32
#define KCH (NN / KS)   // 1024 k-elements per energy split

typedef unsigned long long ull;

// packed fp32x2 FMA: acc = a * b + acc (two independent fp32 lanes)
__device__ __forceinline__ void fma2(ull& acc, ull a, ull b) {
    asm("fma.rn.f32x2 %0, %1, %2, %0;" : "+l"(acc) : "l"(a), "l"(b));
}
__device__ __forceinline__ ull bcast2(float v) {
    ull r;
    asm("mov.b64 %0, {%1, %1};" : "=l"(r) : "f"(v));
    return r;
}
__device__ __forceinline__ void unpack2(float& lo, float& hi, ull p) {
    asm("mov.b64 {%0, %1}, %2;" : "=f"(lo), "=f"(hi) : "l"(p));
}

// ---------------- scratch (static device globals; no allocations) ------------
__device__ float g_xcon[(size_t)BB * C2 * NN];   // [b][d][n]: d<128 = x_q, d>=128 = x_k
__device__ float g_vcon[(size_t)BB * C2 * NN];   // [b][d][n]: d<128 = y_v, d>=128 = x_v
__device__ float g_epart[(size_t)BB * KS * C2 * C2]; // split-K partials
__device__ float g_energy[BB * C2 * C2];
__device__ float g_e1[BB * C2 * C2];
__device__ float g_attn[BB * C2 * CC];           // attn[b][d][c]

// ---------------- kernel 1: four pointwise convs ----------------------------
// grid (N/64, B, 4), block (16,16), dyn smem 96KB
extern "C" __global__ void __launch_bounds__(256, 2)
k_pconv(const float* __restrict__ x, const float* __restrict__ y,
        const float* __restrict__ qw, const float* __restrict__ qb,
        const float* __restrict__ kw, const float* __restrict__ kb,
        const float* __restrict__ v1w, const float* __restrict__ v1b,
        const float* __restrict__ v2w, const float* __restrict__ v2b)
{
    extern __shared__ float sm[];
    float* sWt = sm;             // [k=128][o=128]  (o contiguous -> row pairs)
    float* sX  = sm + 128 * 128; // [k=128][n=64]

    int b  = blockIdx.y;
    int n0 = blockIdx.x * 64;
    int z  = blockIdx.z;

    const float* W; const float* bias; const float* In; float* Out;
    if (z == 0)      { W = qw;  bias = qb;  In = y; Out = g_xcon + (size_t)b * C2 * NN; }
    else if (z == 1) { W = kw;  bias = kb;  In = x; Out = g_xcon + (size_t)b * C2 * NN + (size_t)CC * NN; }
    else if (z == 2) { W = v2w; bias = v2b; In = y; Out = g_vcon + (size_t)b * C2 * NN; }
    else             { W = v1w; bias = v1b; In = x; Out = g_vcon + (size_t)b * C2 * NN + (size_t)CC * NN; }
    In += (size_t)b * CC * NN;

    int tid = threadIdx.y * 16 + threadIdx.x;

    #pragma unroll 8
    for (int t = 0; t < 64; t++) {
        int idx = tid + t * 256;
        int o = idx >> 7, k = idx & 127;
        sWt[k * 128 + o] = W[idx];
    }
    #pragma unroll 8
    for (int t = 0; t < 32; t++) {
        int idx = tid + t * 256;
        int k = idx >> 6, c = idx & 63;
        sX[k * 64 + c] = In[(size_t)k * NN + n0 + c];
    }
    __syncthreads();

    int r0 = threadIdx.y * 8;   // even -> 8B-aligned pairs in sWt
    int c0 = threadIdx.x * 4;

    // acc2[p][j]: rows (r0+2p, r0+2p+1), col c0+j
    ull acc2[4][4];
    #pragma unroll
    for (int p = 0; p < 4; p++)
        #pragma unroll
        for (int j = 0; j < 4; j++) acc2[p][j] = 0ull;

    #pragma unroll 8
    for (int k = 0; k < 128; k++) {
        const ull* ap = (const ull*)(sWt + k * 128 + r0);  // 4 row-pairs
        ull xb[4];
        #pragma unroll
        for (int j = 0; j < 4; j++) xb[j] = bcast2(sX[k * 64 + c0 + j]);
        #pragma unroll
        for (int p = 0; p < 4; p++) {
            ull a = ap[p];
            #pragma unroll
            for (int j = 0; j < 4; j++) fma2(acc2[p][j], a, xb[j]);
        }
    }

    #pragma unroll
    for (int p = 0; p < 4; p++) {
        float b0 = bias[r0 + 2 * p], b1 = bias[r0 + 2 * p + 1];
        #pragma unroll
        for (int j = 0; j < 4; j++) {
            float lo, hi;
            unpack2(lo, hi, acc2[p][j]);
            Out[(size_t)(r0 + 2 * p)     * NN + n0 + c0 + j] = lo + b0;
            Out[(size_t)(r0 + 2 * p + 1) * NN + n0 + c0 + j] = hi + b1;
        }
    }
}

// ---------------- kernel 2: energy split-K partials --------------------------
// grid (4 tiles, KS, B), block (16,16). 128x128 output tile, 8x8 micro.
#define EP 130   // even padding -> LDS.64-aligned pairs
extern "C" __global__ void __launch_bounds__(256, 1)
k_energy()
{
    __shared__ float sAt[32 * EP];
    __shared__ float sBt[32 * EP];

    int b   = blockIdx.z;
    int ksl = blockIdx.y;
    int i0  = (blockIdx.x >> 1) * 128;
    int j0  = (blockIdx.x & 1) * 128;
    const float* A = g_xcon + (size_t)b * C2 * NN;
    int tid = threadIdx.y * 16 + threadIdx.x;
    int k0  = ksl * KCH;

    // acc2[i][jp]: row i (8 rows), col-pairs jp (8 cols as 4 pairs)
    ull acc2[8][4];
    #pragma unroll
    for (int i = 0; i < 8; i++)
        #pragma unroll
        for (int jp = 0; jp < 4; jp++) acc2[i][jp] = 0ull;

    int ty4 = threadIdx.y * 4, tx4 = threadIdx.x * 4;

    for (int kc = 0; kc < KCH; kc += 32) {
        __syncthreads();
        #pragma unroll 4
        for (int t = 0; t < 16; t++) {
            int e = tid + t * 256;
            int r = e >> 5, kk = e & 31;
            sAt[kk * EP + r] = A[(size_t)(i0 + r) * NN + k0 + kc + kk];
            sBt[kk * EP + r] = A[(size_t)(j0 + r) * NN + k0 + kc + kk];
        }
        __syncthreads();
        #pragma unroll
        for (int kk = 0; kk < 32; kk++) {
            ull ab[8];
            #pragma unroll
            for (int q = 0; q < 4; q++) {
                ab[q]     = bcast2(sAt[kk * EP + ty4 + q]);
                ab[4 + q] = bcast2(sAt[kk * EP + 64 + ty4 + q]);
            }
            const ull* bp0 = (const ull*)(sBt + kk * EP + tx4);      // pairs 0,1
            const ull* bp1 = (const ull*)(sBt + kk * EP + 64 + tx4); // pairs 2,3
            ull bv[4] = { bp0[0], bp0[1], bp1[0], bp1[1] };
            #pragma unroll
            for (int i = 0; i < 8; i++)
                #pragma unroll
                for (int jp = 0; jp < 4; jp++)
                    fma2(acc2[i][jp], ab[i], bv[jp]);
        }
    }

    float* Ep = g_epart + ((size_t)(b * KS + ksl) * C2) * C2;
    #pragma unroll
    for (int i = 0; i < 8; i++) {
        int ri = i0 + (i >> 2) * 64 + ty4 + (i & 3);
        #pragma unroll
        for (int jp = 0; jp < 4; jp++) {
            int cj = j0 + (jp >> 1) * 64 + tx4 + (jp & 1) * 2;
            float lo, hi;
            unpack2(lo, hi, acc2[i][jp]);
            Ep[(size_t)ri * C2 + cj]     = lo;
            Ep[(size_t)ri * C2 + cj + 1] = hi;
        }
    }
}

// ---------------- kernel 2b: deterministic split-K reduce + 1/sqrt(2C) ------
extern "C" __global__ void k_ereduce()
{
    int j = threadIdx.x, i = blockIdx.x, b = blockIdx.y;
    size_t base = ((size_t)b * KS * C2 + i) * C2 + j;
    float s = 0.f;
    #pragma unroll 8
    for (int ks = 0; ks < KS; ks++) s += g_epart[base + (size_t)ks * C2 * C2];
    g_energy[((size_t)b * C2 + i) * C2 + j] = s * (1.0f / 16.0f); // sqrt(256)=16
}

// ---------------- kernel 3a: e1 = relu(energy @ t1^T + t1_b) -----------------
// grid (32 rowgroups of 8, B), block 256 (one thread per output col), k paired
extern "C" __global__ void __launch_bounds__(256)
k_mlp1(const float* __restrict__ t1w, const float* __restrict__ t1b)
{
    __shared__ float sE[8 * 256];
    int b = blockIdx.y, rg = blockIdx.x;
    int tid = threadIdx.x;
    const float* E = g_energy + (size_t)b * C2 * C2 + (size_t)rg * 8 * C2;
    #pragma unroll
    for (int t = 0; t < 8; t++) sE[tid + t * 256] = E[tid + t * 256];
    __syncthreads();

    int j = tid;
    ull acc2[8];
    #pragma unroll
    for (int i = 0; i < 8; i++) acc2[i] = 0ull;
    const ull* wrow = (const ull*)(t1w + (size_t)j * C2);  // j*256 floats -> 8B aligned
    #pragma unroll 4
    for (int k2 = 0; k2 < 128; k2++) {
        ull w = wrow[k2];
        #pragma unroll
        for (int i = 0; i < 8; i++) {
            ull e = ((const ull*)(sE + i * 256))[k2];
            fma2(acc2[i], e, w);
        }
    }
    float bv = t1b[j];
    float* O = g_e1 + (size_t)b * C2 * C2 + (size_t)rg * 8 * C2;
    #pragma unroll
    for (int i = 0; i < 8; i++) {
        float lo, hi;
        unpack2(lo, hi, acc2[i]);
        O[i * 256 + j] = fmaxf(lo + hi + bv, 0.f);
    }
}

// ---------------- kernel 3b: e2 + softmax -> attn ---------------------------
// grid (256 rows, B), block 128
extern "C" __global__ void __launch_bounds__(128)
k_mlp2(const float* __restrict__ t2w, const float* __restrict__ t2b)
{
    __shared__ float sR[256];
    __shared__ float red[128];
    int b = blockIdx.y, i = blockIdx.x, j = threadIdx.x;
    const float* E1 = g_e1 + ((size_t)b * C2 + i) * C2;
    sR[j] = E1[j];
    sR[j + 128] = E1[j + 128];
    __syncthreads();

    const float* wrow = t2w + (size_t)j * C2;
    float d = 0.f;
    #pragma unroll 8
    for (int k = 0; k < 256; k++) d += sR[k] * wrow[k];
    float v = fmaxf(d + t2b[j], 0.f);

    red[j] = v; __syncthreads();
    for (int s = 64; s > 0; s >>= 1) {
        if (j < s) red[j] = fmaxf(red[j], red[j + s]);
        __syncthreads();
    }
    float m = red[0]; __syncthreads();
    float e = expf(v - m);
    red[j] = e; __syncthreads();
    for (int s = 64; s > 0; s >>= 1) {
        if (j < s) red[j] += red[j + s];
        __syncthreads();
    }
    float sum = red[0];
    g_attn[((size_t)b * C2 + i) * CC + j] = e / sum;
}

// ---------------- kernel 4: out = attn^T @ vcon ------------------------------
// grid (N/64, B), block (16,16), dyn smem ~144KB
extern "C" __global__ void __launch_bounds__(256, 1)
k_out(float* __restrict__ out)
{
    extern __shared__ float sm[];
    float* sAttn = sm;             // [d=256][c=128] (c contiguous -> row pairs)
    float* sV    = sm + 256 * 128; // [kk=64][n=64] pad 65

    int b = blockIdx.y;
    int n0 = blockIdx.x * 64;
    int tid = threadIdx.y * 16 + threadIdx.x;

    const float* At = g_attn + (size_t)b * C2 * CC;
    for (int t = 0; t < 128; t++) sAttn[tid + t * 256] = At[tid + t * 256];

    const float* V = g_vcon + (size_t)b * C2 * NN;
    int c0r = threadIdx.y * 8;  // even -> aligned pairs in sAttn
    int nl0 = threadIdx.x * 4;

    // acc2[p][j]: out-channel pair (c0r+2p, c0r+2p+1), col nl0+j
    ull acc2[4][4];
    #pragma unroll
    for (int p = 0; p < 4; p++)
        #pragma unroll
        for (int j = 0; j < 4; j++) acc2[p][j] = 0ull;

    for (int dd = 0; dd < 4; dd++) {
        __syncthreads();
        #pragma unroll 4
        for (int t = 0; t < 16; t++) {
            int e = tid + t * 256;
            int kk = e >> 6, c = e & 63;
            sV[kk * 65 + c] = V[(size_t)(dd * 64 + kk) * NN + n0 + c];
        }
        __syncthreads();
        #pragma unroll 4
        for (int kk = 0; kk < 64; kk++) {
            int d = dd * 64 + kk;
            const ull* ap = (const ull*)(sAttn + d * 128 + c0r);  // 4 pairs
            ull vb[4];
            #pragma unroll
            for (int j = 0; j < 4; j++) vb[j] = bcast2(sV[kk * 65 + nl0 + j]);
            #pragma unroll
            for (int p = 0; p < 4; p++) {
                ull a = ap[p];
                #pragma unroll
                for (int j = 0; j < 4; j++) fma2(acc2[p][j], a, vb[j]);
            }
        }
    }

    #pragma unroll
    for (int p = 0; p < 4; p++)
        #pragma unroll
        for (int j = 0; j < 4; j++) {
            float lo, hi;
            unpack2(lo, hi, acc2[p][j]);
            out[((size_t)b * CC + c0r + 2 * p)     * NN + n0 + nl0 + j] = lo;
            out[((size_t)b * CC + c0r + 2 * p + 1) * NN + n0 + nl0 + j] = hi;
        }
}

// ---------------- launch -----------------------------------------------------
extern "C" void kernel_launch(void* const* d_in, const int* in_sizes, int n_in,
                              void* d_out, int out_size)
{
    const float* x   = (const float*)d_in[0];
    const float* y   = (const float*)d_in[1];
    const float* qw  = (const float*)d_in[2];
    const float* qb  = (const float*)d_in[3];
    const float* kw  = (const float*)d_in[4];
    const float* kb  = (const float*)d_in[5];
    const float* v1w = (const float*)d_in[6];
    const float* v1b = (const float*)d_in[7];
    const float* v2w = (const float*)d_in[8];
    const float* v2b = (const float*)d_in[9];
    const float* t1w = (const float*)d_in[10];
    const float* t1b = (const float*)d_in[11];
    const float* t2w = (const float*)d_in[12];
    const float* t2b = (const float*)d_in[13];
    float* out = (float*)d_out;

    cudaFuncSetAttribute(k_pconv, cudaFuncAttributeMaxDynamicSharedMemorySize, 98304);
    cudaFuncSetAttribute(k_out,   cudaFuncAttributeMaxDynamicSharedMemorySize, 147712);

    dim3 b16(16, 16);
    k_pconv <<<dim3(NN / 64, BB, 4), b16, 98304>>>(x, y, qw, qb, kw, kb, v1w, v1b, v2w, v2b);
    k_energy<<<dim3(4, KS, BB), b16>>>();
    k_ereduce<<<dim3(C2, BB), C2>>>();
    k_mlp1  <<<dim3(32, BB), 256>>>(t1w, t1b);
    k_mlp2  <<<dim3(C2, BB), CC>>>(t2w, t2b);
    k_out   <<<dim3(NN / 64, BB), b16, 147712>>>(out);
}

// round 10
// speedup vs baseline: 2.1539x; 2.1539x over previous
#include <cuda_runtime.h>
#include <cuda_bf16.h>
#include <stdint.h>
#include <math.h>

#define BB 8
#define CC 128
#define C2 256
#define NN 32768
#define SPE 16

typedef unsigned int u32;
typedef unsigned long long u64;

// smem geometry: 4 operand planes [128 rows][136 bf16], row stride 272B
#define ST_B 272
#define A_HI 0
#define A_LO 34816
#define B_HI 69632
#define B_LO 104448
#define SM_GEMM 139264

__device__ __forceinline__ u32 smem_u32(const void* p) {
    u32 a;
    asm("{ .reg .u64 t; cvta.to.shared.u64 t, %1; cvt.u32.u64 %0, t; }"
        : "=r"(a) : "l"(p));
    return a;
}

#define LDSM4(r, addr) \
    asm volatile("ldmatrix.sync.aligned.m8n8.x4.shared.b16 {%0,%1,%2,%3}, [%4];" \
        : "=r"((r)[0]), "=r"((r)[1]), "=r"((r)[2]), "=r"((r)[3]) : "r"(addr))

#define MMA(acc, a, b0, b1) \
    asm volatile("mma.sync.aligned.m16n8k16.row.col.f32.bf16.bf16.f32 " \
        "{%0,%1,%2,%3}, {%4,%5,%6,%7}, {%8,%9}, {%0,%1,%2,%3};" \
        : "+f"((acc)[0]), "+f"((acc)[1]), "+f"((acc)[2]), "+f"((acc)[3]) \
        : "r"((a)[0]), "r"((a)[1]), "r"((a)[2]), "r"((a)[3]), "r"(b0), "r"(b1))

// hi/lo bf16 split of two fp32; returns hi pair packed, sets lo pair
__device__ __forceinline__ u32 hilo2(float v0, float v1, u32& lopack) {
    __nv_bfloat16 h0 = __float2bfloat16_rn(v0);
    __nv_bfloat16 h1 = __float2bfloat16_rn(v1);
    __nv_bfloat16 l0 = __float2bfloat16_rn(v0 - __bfloat162float(h0));
    __nv_bfloat16 l1 = __float2bfloat16_rn(v1 - __bfloat162float(h1));
    lopack = (u32)__bfloat16_as_ushort(l0) | ((u32)__bfloat16_as_ushort(l1) << 16);
    return (u32)__bfloat16_as_ushort(h0) | ((u32)__bfloat16_as_ushort(h1) << 16);
}

// ---------------------------------------------------------------- scratch
__device__ __align__(16) __nv_bfloat16 g_xcon_hi[(size_t)BB * C2 * NN]; // [b][d][n]
__device__ __align__(16) __nv_bfloat16 g_xcon_lo[(size_t)BB * C2 * NN];
__device__ __align__(16) __nv_bfloat16 g_vcon_hi[(size_t)BB * NN * C2]; // [b][n][d]
__device__ __align__(16) __nv_bfloat16 g_vcon_lo[(size_t)BB * NN * C2];
__device__ float g_epart[(size_t)BB * SPE * C2 * C2];  // [b][s][i][j]
__device__ float g_energy[BB * C2 * C2];               // [b][i][j]
__device__ float g_e1[BB * C2 * C2];
__device__ float g_attnT[BB * CC * C2];                // [b][c][d]

// ---------------------------------------------------------------- core GEMM
// 128x128 tile, K=128, bf16 hi/lo split (3 products), fp32 acc.
// A smem [m=128][k=128], B smem [n=128][k=128], both k-contiguous, stride 272B.
__device__ __forceinline__ void gemm_tile(u32 sb, u32 ah_off, u32 al_off,
                                          u32 bh_off, u32 bl_off,
                                          float (&acc)[4][4][4],
                                          int wid, int lane)
{
    const int m0 = (wid >> 2) * 64, n0 = (wid & 3) * 32;
    const int row = lane & 15;
    const int half = (lane >> 4) * 16;
    #pragma unroll
    for (int ks = 0; ks < 8; ks++) {
        int kb = ks * 32 + half;
        u32 ah[4][4], al[4][4], bh[2][4], bl[2][4];
        #pragma unroll
        for (int mi = 0; mi < 4; mi++) {
            int ro = (m0 + mi * 16 + row) * ST_B + kb;
            LDSM4(ah[mi], sb + ah_off + ro);
            LDSM4(al[mi], sb + al_off + ro);
        }
        #pragma unroll
        for (int nb = 0; nb < 2; nb++) {
            int ro = (n0 + nb * 16 + row) * ST_B + kb;
            LDSM4(bh[nb], sb + bh_off + ro);
            LDSM4(bl[nb], sb + bl_off + ro);
        }
        #pragma unroll
        for (int mi = 0; mi < 4; mi++)
            #pragma unroll
            for (int ni = 0; ni < 4; ni++) {
                int nb = ni >> 1, sel = ni & 1;
                MMA(acc[mi][ni], ah[mi], bh[nb][sel], bh[nb][sel + 2]);
                MMA(acc[mi][ni], al[mi], bh[nb][sel], bh[nb][sel + 2]);
                MMA(acc[mi][ni], ah[mi], bl[nb][sel], bl[nb][sel + 2]);
            }
    }
}

// ================================================================ kernel 1
// pointwise convs: out[o][n] = W[o][:] . In[:][n] + bias
// grid (256 ntiles, 8, 2 src), block 256.
// src0 (In=x): k_w -> xcon[128..], v1_w -> vcon[..][128..]
// src1 (In=y): q_w -> xcon[0..],   v2_w -> vcon[..][0..]
extern "C" __global__ void __launch_bounds__(256, 1)
k_pconv(const float* __restrict__ x, const float* __restrict__ y,
        const float* __restrict__ qw, const float* __restrict__ qb,
        const float* __restrict__ kw, const float* __restrict__ kb,
        const float* __restrict__ v1w, const float* __restrict__ v1b,
        const float* __restrict__ v2w, const float* __restrict__ v2b)
{
    extern __shared__ char smem[];
    u32 sb = smem_u32(smem);
    int tid = threadIdx.x, wid = tid >> 5, lane = tid & 31;
    int b = blockIdx.y, n0 = blockIdx.x * 128, src = blockIdx.z;
    const float* In = (src ? y : x) + (size_t)b * CC * NN;
    int zoff = src ? 0 : 128;
    float* bias_s = (float*)(smem + SM_GEMM);

    // B = In^T [n][c], hi/lo (coalesced read along n, transposed smem write)
    for (int it = tid; it < 128 * 32; it += 256) {
        int c = it >> 5, j4 = (it & 31) * 4;
        float4 v = *(const float4*)(In + (size_t)c * NN + n0 + j4);
        float vv[4] = {v.x, v.y, v.z, v.w};
        #pragma unroll
        for (int q = 0; q < 4; q++) {
            __nv_bfloat16 h = __float2bfloat16_rn(vv[q]);
            __nv_bfloat16 l = __float2bfloat16_rn(vv[q] - __bfloat162float(h));
            int n = j4 + q;
            *(__nv_bfloat16*)(smem + B_HI + n * ST_B + c * 2) = h;
            *(__nv_bfloat16*)(smem + B_LO + n * ST_B + c * 2) = l;
        }
    }

    for (int zi = 0; zi < 2; zi++) {
        const float* W; const float* bsrc;
        if (src == 0) { W = zi ? v1w : kw; bsrc = zi ? v1b : kb; }
        else          { W = zi ? v2w : qw; bsrc = zi ? v2b : qb; }
        __syncthreads();  // A region free (prev gemm / staging done)
        for (int it = tid; it < 128 * 32; it += 256) {
            int o = it >> 5, c4 = (it & 31) * 4;
            float4 v = *(const float4*)(W + o * 128 + c4);
            u32 l01, h01 = hilo2(v.x, v.y, l01);
            u32 l23, h23 = hilo2(v.z, v.w, l23);
            *(u32*)(smem + A_HI + o * ST_B + c4 * 2)     = h01;
            *(u32*)(smem + A_HI + o * ST_B + c4 * 2 + 4) = h23;
            *(u32*)(smem + A_LO + o * ST_B + c4 * 2)     = l01;
            *(u32*)(smem + A_LO + o * ST_B + c4 * 2 + 4) = l23;
        }
        if (tid < 128) bias_s[tid] = bsrc[tid];
        __syncthreads();

        float acc[4][4][4];
        #pragma unroll
        for (int i = 0; i < 4; i++)
            #pragma unroll
            for (int j = 0; j < 4; j++)
                #pragma unroll
                for (int e = 0; e < 4; e++) acc[i][j][e] = 0.f;

        gemm_tile(sb, A_HI, A_LO, B_HI, B_LO, acc, wid, lane);

        int m0w = (wid >> 2) * 64, n0w = (wid & 3) * 32;
        int r = lane >> 2, cpo = (lane & 3) * 2;

        if (zi == 0) {
            // direct: xcon[zoff+o][n0+n], n pairs -> u32 stores
            #pragma unroll
            for (int mi = 0; mi < 4; mi++) {
                int o = m0w + mi * 16 + r;
                float bb0 = bias_s[o], bb8 = bias_s[o + 8];
                #pragma unroll
                for (int ni = 0; ni < 4; ni++) {
                    int n = n0w + ni * 8 + cpo;
                    u32 lp, hp;
                    hp = hilo2(acc[mi][ni][0] + bb0, acc[mi][ni][1] + bb0, lp);
                    size_t gi = ((size_t)(b * C2 + zoff + o)) * NN + n0 + n;
                    *(u32*)&g_xcon_hi[gi] = hp;
                    *(u32*)&g_xcon_lo[gi] = lp;
                    hp = hilo2(acc[mi][ni][2] + bb8, acc[mi][ni][3] + bb8, lp);
                    gi = ((size_t)(b * C2 + zoff + o + 8)) * NN + n0 + n;
                    *(u32*)&g_xcon_hi[gi] = hp;
                    *(u32*)&g_xcon_lo[gi] = lp;
                }
            }
        } else {
            // transpose to vcon[n0+n][zoff+o] via smem staging, hi then lo
            #pragma unroll
            for (int p = 0; p < 2; p++) {
                __syncthreads();
                #pragma unroll
                for (int mi = 0; mi < 4; mi++) {
                    int o = m0w + mi * 16 + r;
                    float bb0 = bias_s[o], bb8 = bias_s[o + 8];
                    #pragma unroll
                    for (int ni = 0; ni < 4; ni++) {
                        int n = n0w + ni * 8 + cpo;
                        #pragma unroll
                        for (int e = 0; e < 4; e++) {
                            float v = acc[mi][ni][e] + ((e >= 2) ? bb8 : bb0);
                            __nv_bfloat16 h = __float2bfloat16_rn(v);
                            __nv_bfloat16 w = (p == 0) ? h :
                                __float2bfloat16_rn(v - __bfloat162float(h));
                            int oo = o + ((e >= 2) ? 8 : 0);
                            int nn = n + (e & 1);
                            *(__nv_bfloat16*)(smem + A_HI + nn * ST_B + oo * 2) = w;
                        }
                    }
                }
                __syncthreads();
                __nv_bfloat16* dst = (p == 0) ? g_vcon_hi : g_vcon_lo;
                for (int it = tid; it < 128 * 64; it += 256) {
                    int n = it >> 6, w = it & 63;
                    u32 val = *(u32*)(smem + A_HI + n * ST_B + w * 4);
                    *((u32*)(dst + ((size_t)(b * NN + n0 + n)) * C2 + zoff) + w) = val;
                }
            }
        }
    }
}

// ================================================================ kernel 2
// energy Gram: 3 quadrant tiles x 16 K-splits per b. grid (48, 8), block 256.
// t=0:(0,0) t=1:(0,128) t=2:(128,128); diagonal tiles alias A as B.
extern "C" __global__ void __launch_bounds__(256, 1)
k_energy()
{
    extern __shared__ char smem[];
    u32 sb = smem_u32(smem);
    int tid = threadIdx.x, wid = tid >> 5, lane = tid & 31;
    int b = blockIdx.y;
    int t = blockIdx.x >> 4, sp = blockIdx.x & 15;
    int i0 = (t == 2) ? 128 : 0;
    int j0 = (t == 0) ? 0 : 128;
    bool diag = (t != 1);
    const __nv_bfloat16* Xh = g_xcon_hi + (size_t)b * C2 * NN;
    const __nv_bfloat16* Xl = g_xcon_lo + (size_t)b * C2 * NN;

    float acc[4][4][4];
    #pragma unroll
    for (int i = 0; i < 4; i++)
        #pragma unroll
        for (int j = 0; j < 4; j++)
            #pragma unroll
            for (int e = 0; e < 4; e++) acc[i][j][e] = 0.f;

    for (int ch = 0; ch < 16; ch++) {
        __syncthreads();
        int kb = sp * 2048 + ch * 128;
        for (int it = tid; it < 128 * 32; it += 256) {
            int rr = it >> 5, k4 = (it & 31) * 4;
            int so = rr * ST_B + k4 * 2;
            *(u64*)(smem + A_HI + so) = *(const u64*)(Xh + (size_t)(i0 + rr) * NN + kb + k4);
            *(u64*)(smem + A_LO + so) = *(const u64*)(Xl + (size_t)(i0 + rr) * NN + kb + k4);
            if (!diag) {
                *(u64*)(smem + B_HI + so) = *(const u64*)(Xh + (size_t)(j0 + rr) * NN + kb + k4);
                *(u64*)(smem + B_LO + so) = *(const u64*)(Xl + (size_t)(j0 + rr) * NN + kb + k4);
            }
        }
        __syncthreads();
        gemm_tile(sb, A_HI, A_LO, diag ? A_HI : B_HI, diag ? A_LO : B_LO,
                  acc, wid, lane);
    }

    int m0w = (wid >> 2) * 64, n0w = (wid & 3) * 32;
    int r = lane >> 2, cpo = (lane & 3) * 2;
    float* Ep = g_epart + ((size_t)(b * SPE + sp)) * C2 * C2;
    #pragma unroll
    for (int mi = 0; mi < 4; mi++) {
        int i = i0 + m0w + mi * 16 + r;
        #pragma unroll
        for (int ni = 0; ni < 4; ni++) {
            int j = j0 + n0w + ni * 8 + cpo;
            float2 v0 = make_float2(acc[mi][ni][0], acc[mi][ni][1]);
            float2 v1 = make_float2(acc[mi][ni][2], acc[mi][ni][3]);
            *(float2*)&Ep[(size_t)i * C2 + j] = v0;
            *(float2*)&Ep[(size_t)(i + 8) * C2 + j] = v1;
        }
    }
}

// ================================================================ kernel 2b
extern "C" __global__ void k_ereduce()
{
    int j = threadIdx.x, i = blockIdx.x, b = blockIdx.y;
    int si = i, sj = j;
    if (i >= 128 && j < 128) { si = j; sj = i; }  // mirrored quadrant
    size_t base = ((size_t)(b * SPE) * C2 + si) * C2 + sj;
    float s = 0.f;
    #pragma unroll
    for (int sp = 0; sp < SPE; sp++) s += g_epart[base + (size_t)sp * C2 * C2];
    g_energy[((size_t)b * C2 + i) * C2 + j] = s * (1.0f / 16.0f);
}

// ================================================================ kernel 3a
typedef unsigned long long ull;
__device__ __forceinline__ void fma2(ull& acc, ull a, ull b) {
    asm("fma.rn.f32x2 %0, %1, %2, %0;" : "+l"(acc) : "l"(a), "l"(b));
}
__device__ __forceinline__ void unpack2(float& lo, float& hi, ull p) {
    asm("mov.b64 {%0, %1}, %2;" : "=f"(lo), "=f"(hi) : "l"(p));
}

extern "C" __global__ void __launch_bounds__(256)
k_mlp1(const float* __restrict__ t1w, const float* __restrict__ t1b)
{
    __shared__ float sE[8 * 256];
    int b = blockIdx.y, rg = blockIdx.x;
    int tid = threadIdx.x;
    const float* E = g_energy + (size_t)b * C2 * C2 + (size_t)rg * 8 * C2;
    #pragma unroll
    for (int t = 0; t < 8; t++) sE[tid + t * 256] = E[tid + t * 256];
    __syncthreads();

    int j = tid;
    ull acc2[8];
    #pragma unroll
    for (int i = 0; i < 8; i++) acc2[i] = 0ull;
    const ull* wrow = (const ull*)(t1w + (size_t)j * C2);
    #pragma unroll 4
    for (int k2 = 0; k2 < 128; k2++) {
        ull w = wrow[k2];
        #pragma unroll
        for (int i = 0; i < 8; i++) {
            ull e = ((const ull*)(sE + i * 256))[k2];
            fma2(acc2[i], e, w);
        }
    }
    float bv = t1b[j];
    float* O = g_e1 + (size_t)b * C2 * C2 + (size_t)rg * 8 * C2;
    #pragma unroll
    for (int i = 0; i < 8; i++) {
        float lo, hi;
        unpack2(lo, hi, acc2[i]);
        O[i * 256 + j] = fmaxf(lo + hi + bv, 0.f);
    }
}

// ================================================================ kernel 3b
// e2 + softmax, writes attn TRANSPOSED: attnT[c][d]
extern "C" __global__ void __launch_bounds__(128)
k_mlp2(const float* __restrict__ t2w, const float* __restrict__ t2b)
{
    __shared__ float sR[256];
    __shared__ float red[128];
    int b = blockIdx.y, i = blockIdx.x, j = threadIdx.x;
    const float* E1 = g_e1 + ((size_t)b * C2 + i) * C2;
    sR[j] = E1[j];
    sR[j + 128] = E1[j + 128];
    __syncthreads();

    const float* wrow = t2w + (size_t)j * C2;
    float d = 0.f;
    #pragma unroll 8
    for (int k = 0; k < 256; k++) d += sR[k] * wrow[k];
    float v = fmaxf(d + t2b[j], 0.f);

    red[j] = v; __syncthreads();
    for (int s = 64; s > 0; s >>= 1) {
        if (j < s) red[j] = fmaxf(red[j], red[j + s]);
        __syncthreads();
    }
    float m = red[0]; __syncthreads();
    float e = expf(v - m);
    red[j] = e; __syncthreads();
    for (int s = 64; s > 0; s >>= 1) {
        if (j < s) red[j] += red[j + s];
        __syncthreads();
    }
    float sum = red[0];
    g_attnT[((size_t)b * CC + j) * C2 + i] = e / sum;
}

// ================================================================ kernel 4
// out[c][n] = sum_d attnT[c][d] * vcon[n][d]. grid (256 ntiles, 8), block 256.
extern "C" __global__ void __launch_bounds__(256, 1)
k_out(float* __restrict__ out)
{
    extern __shared__ char smem[];
    u32 sb = smem_u32(smem);
    int tid = threadIdx.x, wid = tid >> 5, lane = tid & 31;
    int b = blockIdx.y, n0 = blockIdx.x * 128;
    const float* At = g_attnT + (size_t)b * CC * C2;
    const __nv_bfloat16* Vh = g_vcon_hi + (size_t)b * NN * C2;
    const __nv_bfloat16* Vl = g_vcon_lo + (size_t)b * NN * C2;

    float acc[4][4][4];
    #pragma unroll
    for (int i = 0; i < 4; i++)
        #pragma unroll
        for (int j = 0; j < 4; j++)
            #pragma unroll
            for (int e = 0; e < 4; e++) acc[i][j][e] = 0.f;

    for (int ch = 0; ch < 2; ch++) {
        __syncthreads();
        int k0 = ch * 128;
        // A = attnT rows [c][d-chunk], fp32 -> hi/lo
        for (int it = tid; it < 128 * 32; it += 256) {
            int c = it >> 5, d4 = (it & 31) * 4;
            float4 v = *(const float4*)(At + (size_t)c * C2 + k0 + d4);
            u32 l01, h01 = hilo2(v.x, v.y, l01);
            u32 l23, h23 = hilo2(v.z, v.w, l23);
            *(u32*)(smem + A_HI + c * ST_B + d4 * 2)     = h01;
            *(u32*)(smem + A_HI + c * ST_B + d4 * 2 + 4) = h23;
            *(u32*)(smem + A_LO + c * ST_B + d4 * 2)     = l01;
            *(u32*)(smem + A_LO + c * ST_B + d4 * 2 + 4) = l23;
        }
        // B = vcon rows [n][d-chunk], already bf16 hi/lo
        for (int it = tid; it < 128 * 32; it += 256) {
            int n = it >> 5, d4 = (it & 31) * 4;
            int so = n * ST_B + d4 * 2;
            size_t gi = (size_t)(n0 + n) * C2 + k0 + d4;
            *(u64*)(smem + B_HI + so) = *(const u64*)(Vh + gi);
            *(u64*)(smem + B_LO + so) = *(const u64*)(Vl + gi);
        }
        __syncthreads();
        gemm_tile(sb, A_HI, A_LO, B_HI, B_LO, acc, wid, lane);
    }

    int m0w = (wid >> 2) * 64, n0w = (wid & 3) * 32;
    int r = lane >> 2, cpo = (lane & 3) * 2;
    #pragma unroll
    for (int mi = 0; mi < 4; mi++) {
        int m = m0w + mi * 16 + r;
        #pragma unroll
        for (int ni = 0; ni < 4; ni++) {
            int n = n0w + ni * 8 + cpo;
            float2 v0 = make_float2(acc[mi][ni][0], acc[mi][ni][1]);
            float2 v1 = make_float2(acc[mi][ni][2], acc[mi][ni][3]);
            *(float2*)&out[((size_t)(b * CC + m)) * NN + n0 + n] = v0;
            *(float2*)&out[((size_t)(b * CC + m + 8)) * NN + n0 + n] = v1;
        }
    }
}

// ---------------------------------------------------------------- launch
extern "C" void kernel_launch(void* const* d_in, const int* in_sizes, int n_in,
                              void* d_out, int out_size)
{
    const float* x   = (const float*)d_in[0];
    const float* y   = (const float*)d_in[1];
    const float* qw  = (const float*)d_in[2];
    const float* qb  = (const float*)d_in[3];
    const float* kw  = (const float*)d_in[4];
    const float* kb  = (const float*)d_in[5];
    const float* v1w = (const float*)d_in[6];
    const float* v1b = (const float*)d_in[7];
    const float* v2w = (const float*)d_in[8];
    const float* v2b = (const float*)d_in[9];
    const float* t1w = (const float*)d_in[10];
    const float* t1b = (const float*)d_in[11];
    const float* t2w = (const float*)d_in[12];
    const float* t2b = (const float*)d_in[13];
    float* out = (float*)d_out;

    cudaFuncSetAttribute(k_pconv,  cudaFuncAttributeMaxDynamicSharedMemorySize, SM_GEMM + 512);
    cudaFuncSetAttribute(k_energy, cudaFuncAttributeMaxDynamicSharedMemorySize, SM_GEMM);
    cudaFuncSetAttribute(k_out,    cudaFuncAttributeMaxDynamicSharedMemorySize, SM_GEMM);

    k_pconv <<<dim3(NN / 128, BB, 2), 256, SM_GEMM + 512>>>(x, y, qw, qb, kw, kb,
                                                            v1w, v1b, v2w, v2b);
    k_energy<<<dim3(3 * SPE, BB), 256, SM_GEMM>>>();
    k_ereduce<<<dim3(C2, BB), C2>>>();
    k_mlp1  <<<dim3(32, BB), 256>>>(t1w, t1b);
    k_mlp2  <<<dim3(C2, BB), CC>>>(t2w, t2b);
    k_out   <<<dim3(NN / 128, BB), 256, SM_GEMM>>>(out);
}

// round 12
// speedup vs baseline: 2.6563x; 1.2332x over previous
#include <cuda_runtime.h>
#include <cuda_bf16.h>
#include <cuda_fp16.h>
#include <stdint.h>
#include <math.h>

#define BB 8
#define CC 128
#define C2 256
#define NN 32768
#define SPE 16

typedef unsigned int u32;
typedef unsigned long long u64;

// smem plane geometry: [128 rows][136 elems of 2B], row stride 272B
#define ST_B 272
#define A_HI 0
#define A_LO 34816
#define B_HI 69632
#define B_LO 104448
#define B_F16 139264
#define SM_PCONV (B_F16 + 34816 + 512)   // 5 planes + bias
#define SM_4PL 139264                     // energy: 4 planes
#define SM_2PL 69632                      // out: 2 planes

__device__ __forceinline__ u32 smem_u32(const void* p) {
    u32 a;
    asm("{ .reg .u64 t; cvta.to.shared.u64 t, %1; cvt.u32.u64 %0, t; }"
        : "=r"(a) : "l"(p));
    return a;
}

#define LDSM4(r, addr) \
    asm volatile("ldmatrix.sync.aligned.m8n8.x4.shared.b16 {%0,%1,%2,%3}, [%4];" \
        : "=r"((r)[0]), "=r"((r)[1]), "=r"((r)[2]), "=r"((r)[3]) : "r"(addr))

#define MMA_BF(acc, a, b0, b1) \
    asm volatile("mma.sync.aligned.m16n8k16.row.col.f32.bf16.bf16.f32 " \
        "{%0,%1,%2,%3}, {%4,%5,%6,%7}, {%8,%9}, {%0,%1,%2,%3};" \
        : "+f"((acc)[0]), "+f"((acc)[1]), "+f"((acc)[2]), "+f"((acc)[3]) \
        : "r"((a)[0]), "r"((a)[1]), "r"((a)[2]), "r"((a)[3]), "r"(b0), "r"(b1))

#define MMA_FP(acc, a, b0, b1) \
    asm volatile("mma.sync.aligned.m16n8k16.row.col.f32.f16.f16.f32 " \
        "{%0,%1,%2,%3}, {%4,%5,%6,%7}, {%8,%9}, {%0,%1,%2,%3};" \
        : "+f"((acc)[0]), "+f"((acc)[1]), "+f"((acc)[2]), "+f"((acc)[3]) \
        : "r"((a)[0]), "r"((a)[1]), "r"((a)[2]), "r"((a)[3]), "r"(b0), "r"(b1))

__device__ __forceinline__ u32 packh2(float a, float b) {
    __half2 h = __floats2half2_rn(a, b);
    return *(u32*)&h;
}
__device__ __forceinline__ u32 hilo2(float v0, float v1, u32& lopack) {
    __nv_bfloat16 h0 = __float2bfloat16_rn(v0);
    __nv_bfloat16 h1 = __float2bfloat16_rn(v1);
    __nv_bfloat16 l0 = __float2bfloat16_rn(v0 - __bfloat162float(h0));
    __nv_bfloat16 l1 = __float2bfloat16_rn(v1 - __bfloat162float(h1));
    lopack = (u32)__bfloat16_as_ushort(l0) | ((u32)__bfloat16_as_ushort(l1) << 16);
    return (u32)__bfloat16_as_ushort(h0) | ((u32)__bfloat16_as_ushort(h1) << 16);
}

// ---------------------------------------------------------------- scratch
__device__ __align__(16) __nv_bfloat16 g_xcon_hi[(size_t)BB * C2 * NN]; // [b][d][n]
__device__ __align__(16) __nv_bfloat16 g_xcon_lo[(size_t)BB * C2 * NN];
__device__ __align__(16) __half g_vcon[(size_t)BB * NN * C2];           // [b][n][d]
__device__ float g_epart[(size_t)BB * SPE * C2 * C2];                   // [b][s][i][j]
__device__ float g_energy[BB * C2 * C2];
__device__ float g_e1[BB * C2 * C2];
__device__ float g_attnT[BB * CC * C2];                                 // [b][c][d]

// ---------------------------------------------------------------- GEMM cores
// 128x128 tile, K=128; A [m][k], B [n][k], k-contiguous, stride 272B.
__device__ __forceinline__ void gemm3_bf16(u32 sb, u32 ah_off, u32 al_off,
                                           u32 bh_off, u32 bl_off,
                                           float (&acc)[4][4][4],
                                           int wid, int lane)
{
    const int m0 = (wid >> 2) * 64, n0 = (wid & 3) * 32;
    const int row = lane & 15;
    const int half = (lane >> 4) * 16;
    #pragma unroll
    for (int ks = 0; ks < 8; ks++) {
        int kb = ks * 32 + half;
        u32 ah[4][4], al[4][4], bh[2][4], bl[2][4];
        #pragma unroll
        for (int mi = 0; mi < 4; mi++) {
            int ro = (m0 + mi * 16 + row) * ST_B + kb;
            LDSM4(ah[mi], sb + ah_off + ro);
            LDSM4(al[mi], sb + al_off + ro);
        }
        #pragma unroll
        for (int nb = 0; nb < 2; nb++) {
            int ro = (n0 + nb * 16 + row) * ST_B + kb;
            LDSM4(bh[nb], sb + bh_off + ro);
            LDSM4(bl[nb], sb + bl_off + ro);
        }
        #pragma unroll
        for (int mi = 0; mi < 4; mi++)
            #pragma unroll
            for (int ni = 0; ni < 4; ni++) {
                int nb = ni >> 1, sel = ni & 1;
                MMA_BF(acc[mi][ni], ah[mi], bh[nb][sel], bh[nb][sel + 2]);
                MMA_BF(acc[mi][ni], al[mi], bh[nb][sel], bh[nb][sel + 2]);
                MMA_BF(acc[mi][ni], ah[mi], bl[nb][sel], bl[nb][sel + 2]);
            }
    }
}

__device__ __forceinline__ void gemm1_f16(u32 sb, u32 a_off, u32 b_off,
                                          float (&acc)[4][4][4],
                                          int wid, int lane)
{
    const int m0 = (wid >> 2) * 64, n0 = (wid & 3) * 32;
    const int row = lane & 15;
    const int half = (lane >> 4) * 16;
    #pragma unroll
    for (int ks = 0; ks < 8; ks++) {
        int kb = ks * 32 + half;
        u32 ah[4][4], bh[2][4];
        #pragma unroll
        for (int mi = 0; mi < 4; mi++)
            LDSM4(ah[mi], sb + a_off + (m0 + mi * 16 + row) * ST_B + kb);
        #pragma unroll
        for (int nb = 0; nb < 2; nb++)
            LDSM4(bh[nb], sb + b_off + (n0 + nb * 16 + row) * ST_B + kb);
        #pragma unroll
        for (int mi = 0; mi < 4; mi++)
            #pragma unroll
            for (int ni = 0; ni < 4; ni++) {
                int nb = ni >> 1, sel = ni & 1;
                MMA_FP(acc[mi][ni], ah[mi], bh[nb][sel], bh[nb][sel + 2]);
            }
    }
}

// ================================================================ kernel 1
// grid (256 ntiles, 8, 2 src), block 256.
// src0 (In=x): k_w -> xcon[128..] (bf16 3x), v1_w -> vcon[..][128..] (fp16 1x)
// src1 (In=y): q_w -> xcon[0..]   (bf16 3x), v2_w -> vcon[..][0..]   (fp16 1x)
extern "C" __global__ void __launch_bounds__(256, 1)
k_pconv(const float* __restrict__ x, const float* __restrict__ y,
        const float* __restrict__ qw, const float* __restrict__ qb,
        const float* __restrict__ kw, const float* __restrict__ kb,
        const float* __restrict__ v1w, const float* __restrict__ v1b,
        const float* __restrict__ v2w, const float* __restrict__ v2b)
{
    extern __shared__ char smem[];
    u32 sb = smem_u32(smem);
    int tid = threadIdx.x, wid = tid >> 5, lane = tid & 31;
    int b = blockIdx.y, n0 = blockIdx.x * 128, src = blockIdx.z;
    const float* In = (src ? y : x) + (size_t)b * CC * NN;
    int zoff = src ? 0 : 128;
    float* bias_s = (float*)(smem + SM_PCONV - 512);

    // B = In^T [n][c]: bf16 hi/lo + fp16 planes (n spread mod 32 across lanes)
    for (int it = tid; it < 128 * 32; it += 256) {
        int c = it >> 5, j = it & 31;
        #pragma unroll
        for (int q = 0; q < 4; q++) {
            int n = j + q * 32;
            float v = In[(size_t)c * NN + n0 + n];
            __nv_bfloat16 h = __float2bfloat16_rn(v);
            __nv_bfloat16 l = __float2bfloat16_rn(v - __bfloat162float(h));
            *(__nv_bfloat16*)(smem + B_HI + n * ST_B + c * 2) = h;
            *(__nv_bfloat16*)(smem + B_LO + n * ST_B + c * 2) = l;
            *(__half*)(smem + B_F16 + n * ST_B + c * 2) = __float2half_rn(v);
        }
    }

    for (int zi = 0; zi < 2; zi++) {
        const float* W; const float* bsrc;
        if (src == 0) { W = zi ? v1w : kw; bsrc = zi ? v1b : kb; }
        else          { W = zi ? v2w : qw; bsrc = zi ? v2b : qb; }
        __syncthreads();   // prior gemm reads of A planes complete
        if (zi == 0) {
            for (int it = tid; it < 128 * 32; it += 256) {
                int o = it >> 5, c4 = (it & 31) * 4;
                float4 v = *(const float4*)(W + o * 128 + c4);
                u32 l01, h01 = hilo2(v.x, v.y, l01);
                u32 l23, h23 = hilo2(v.z, v.w, l23);
                *(u32*)(smem + A_HI + o * ST_B + c4 * 2)     = h01;
                *(u32*)(smem + A_HI + o * ST_B + c4 * 2 + 4) = h23;
                *(u32*)(smem + A_LO + o * ST_B + c4 * 2)     = l01;
                *(u32*)(smem + A_LO + o * ST_B + c4 * 2 + 4) = l23;
            }
        } else {
            for (int it = tid; it < 128 * 32; it += 256) {
                int o = it >> 5, c4 = (it & 31) * 4;
                float4 v = *(const float4*)(W + o * 128 + c4);
                *(u32*)(smem + A_HI + o * ST_B + c4 * 2)     = packh2(v.x, v.y);
                *(u32*)(smem + A_HI + o * ST_B + c4 * 2 + 4) = packh2(v.z, v.w);
            }
        }
        if (tid < 128) bias_s[tid] = bsrc[tid];
        __syncthreads();

        float acc[4][4][4];
        #pragma unroll
        for (int i = 0; i < 4; i++)
            #pragma unroll
            for (int j = 0; j < 4; j++)
                #pragma unroll
                for (int e = 0; e < 4; e++) acc[i][j][e] = 0.f;

        if (zi == 0) gemm3_bf16(sb, A_HI, A_LO, B_HI, B_LO, acc, wid, lane);
        else         gemm1_f16(sb, A_HI, B_F16, acc, wid, lane);

        int m0w = (wid >> 2) * 64, n0w = (wid & 3) * 32;
        int r = lane >> 2, cpo = (lane & 3) * 2;

        if (zi == 0) {
            // xcon[zoff+o][n0+n], bf16 hi/lo, n-pair u32 stores
            #pragma unroll
            for (int mi = 0; mi < 4; mi++) {
                int o = m0w + mi * 16 + r;
                float bb0 = bias_s[o], bb8 = bias_s[o + 8];
                #pragma unroll
                for (int ni = 0; ni < 4; ni++) {
                    int n = n0w + ni * 8 + cpo;
                    u32 lp, hp;
                    hp = hilo2(acc[mi][ni][0] + bb0, acc[mi][ni][1] + bb0, lp);
                    size_t gi = ((size_t)(b * C2 + zoff + o)) * NN + n0 + n;
                    *(u32*)&g_xcon_hi[gi] = hp;
                    *(u32*)&g_xcon_lo[gi] = lp;
                    hp = hilo2(acc[mi][ni][2] + bb8, acc[mi][ni][3] + bb8, lp);
                    gi = ((size_t)(b * C2 + zoff + o + 8)) * NN + n0 + n;
                    *(u32*)&g_xcon_hi[gi] = hp;
                    *(u32*)&g_xcon_lo[gi] = lp;
                }
            }
        } else {
            // transpose to vcon[n0+n][zoff+o] (fp16) via smem staging in A plane
            __syncthreads();
            #pragma unroll
            for (int mi = 0; mi < 4; mi++) {
                int o = m0w + mi * 16 + r;
                float bb0 = bias_s[o], bb8 = bias_s[o + 8];
                #pragma unroll
                for (int ni = 0; ni < 4; ni++) {
                    int n = n0w + ni * 8 + cpo;
                    #pragma unroll
                    for (int e = 0; e < 4; e++) {
                        float v = acc[mi][ni][e] + ((e >= 2) ? bb8 : bb0);
                        int oo = o + ((e >= 2) ? 8 : 0);
                        int nn = n + (e & 1);
                        *(__half*)(smem + A_HI + nn * ST_B + oo * 2) =
                            __float2half_rn(v);
                    }
                }
            }
            __syncthreads();
            for (int it = tid; it < 128 * 64; it += 256) {
                int n = it >> 6, w = it & 63;
                u32 val = *(u32*)(smem + A_HI + n * ST_B + w * 4);
                *((u32*)(g_vcon + ((size_t)(b * NN + n0 + n)) * C2 + zoff) + w) = val;
            }
        }
    }
}

// ================================================================ kernel 2
// energy Gram (bf16 3x): 3 quadrant tiles x 16 K-splits. grid (48, 8), block 256.
extern "C" __global__ void __launch_bounds__(256, 1)
k_energy()
{
    extern __shared__ char smem[];
    u32 sb = smem_u32(smem);
    int tid = threadIdx.x, wid = tid >> 5, lane = tid & 31;
    int b = blockIdx.y;
    int t = blockIdx.x >> 4, sp = blockIdx.x & 15;
    int i0 = (t == 2) ? 128 : 0;
    int j0 = (t == 0) ? 0 : 128;
    bool diag = (t != 1);
    const __nv_bfloat16* Xh = g_xcon_hi + (size_t)b * C2 * NN;
    const __nv_bfloat16* Xl = g_xcon_lo + (size_t)b * C2 * NN;

    float acc[4][4][4];
    #pragma unroll
    for (int i = 0; i < 4; i++)
        #pragma unroll
        for (int j = 0; j < 4; j++)
            #pragma unroll
            for (int e = 0; e < 4; e++) acc[i][j][e] = 0.f;

    for (int ch = 0; ch < 16; ch++) {
        __syncthreads();
        int kb = sp * 2048 + ch * 128;
        for (int it = tid; it < 128 * 16; it += 256) {
            int r = it >> 4, seg = it & 15;
            *(uint4*)(smem + A_HI + r * ST_B + seg * 16) =
                *((const uint4*)(Xh + (size_t)(i0 + r) * NN + kb) + seg);
            *(uint4*)(smem + A_LO + r * ST_B + seg * 16) =
                *((const uint4*)(Xl + (size_t)(i0 + r) * NN + kb) + seg);
            if (!diag) {
                *(uint4*)(smem + B_HI + r * ST_B + seg * 16) =
                    *((const uint4*)(Xh + (size_t)(j0 + r) * NN + kb) + seg);
                *(uint4*)(smem + B_LO + r * ST_B + seg * 16) =
                    *((const uint4*)(Xl + (size_t)(j0 + r) * NN + kb) + seg);
            }
        }
        __syncthreads();
        gemm3_bf16(sb, A_HI, A_LO, diag ? A_HI : B_HI, diag ? A_LO : B_LO,
                   acc, wid, lane);
    }

    int m0w = (wid >> 2) * 64, n0w = (wid & 3) * 32;
    int r = lane >> 2, cpo = (lane & 3) * 2;
    float* Ep = g_epart + ((size_t)(b * SPE + sp)) * C2 * C2;
    #pragma unroll
    for (int mi = 0; mi < 4; mi++) {
        int i = i0 + m0w + mi * 16 + r;
        #pragma unroll
        for (int ni = 0; ni < 4; ni++) {
            int j = j0 + n0w + ni * 8 + cpo;
            *(float2*)&Ep[(size_t)i * C2 + j] =
                make_float2(acc[mi][ni][0], acc[mi][ni][1]);
            *(float2*)&Ep[(size_t)(i + 8) * C2 + j] =
                make_float2(acc[mi][ni][2], acc[mi][ni][3]);
        }
    }
}

// ================================================================ kernel 2b
extern "C" __global__ void k_ereduce()
{
    int j = threadIdx.x, i = blockIdx.x, b = blockIdx.y;
    int si = i, sj = j;
    if (i >= 128 && j < 128) { si = j; sj = i; }
    size_t base = ((size_t)(b * SPE) * C2 + si) * C2 + sj;
    float s = 0.f;
    #pragma unroll
    for (int sp = 0; sp < SPE; sp++) s += g_epart[base + (size_t)sp * C2 * C2];
    g_energy[((size_t)b * C2 + i) * C2 + j] = s * (1.0f / 16.0f);
}

// ================================================================ kernel 3a
typedef unsigned long long ull;
__device__ __forceinline__ void fma2(ull& acc, ull a, ull b) {
    asm("fma.rn.f32x2 %0, %1, %2, %0;" : "+l"(acc) : "l"(a), "l"(b));
}
__device__ __forceinline__ void unpack2(float& lo, float& hi, ull p) {
    asm("mov.b64 {%0, %1}, %2;" : "=f"(lo), "=f"(hi) : "l"(p));
}

extern "C" __global__ void __launch_bounds__(256)
k_mlp1(const float* __restrict__ t1w, const float* __restrict__ t1b)
{
    __shared__ float sE[8 * 256];
    int b = blockIdx.y, rg = blockIdx.x;
    int tid = threadIdx.x;
    const float* E = g_energy + (size_t)b * C2 * C2 + (size_t)rg * 8 * C2;
    #pragma unroll
    for (int t = 0; t < 8; t++) sE[tid + t * 256] = E[tid + t * 256];
    __syncthreads();

    int j = tid;
    ull acc2[8];
    #pragma unroll
    for (int i = 0; i < 8; i++) acc2[i] = 0ull;
    const ull* wrow = (const ull*)(t1w + (size_t)j * C2);
    #pragma unroll 4
    for (int k2 = 0; k2 < 128; k2++) {
        ull w = wrow[k2];
        #pragma unroll
        for (int i = 0; i < 8; i++) {
            ull e = ((const ull*)(sE + i * 256))[k2];
            fma2(acc2[i], e, w);
        }
    }
    float bv = t1b[j];
    float* O = g_e1 + (size_t)b * C2 * C2 + (size_t)rg * 8 * C2;
    #pragma unroll
    for (int i = 0; i < 8; i++) {
        float lo, hi;
        unpack2(lo, hi, acc2[i]);
        O[i * 256 + j] = fmaxf(lo + hi + bv, 0.f);
    }
}

// ================================================================ kernel 3b
extern "C" __global__ void __launch_bounds__(128)
k_mlp2(const float* __restrict__ t2w, const float* __restrict__ t2b)
{
    __shared__ float sR[256];
    __shared__ float red[128];
    int b = blockIdx.y, i = blockIdx.x, j = threadIdx.x;
    const float* E1 = g_e1 + ((size_t)b * C2 + i) * C2;
    sR[j] = E1[j];
    sR[j + 128] = E1[j + 128];
    __syncthreads();

    const float* wrow = t2w + (size_t)j * C2;
    float d = 0.f;
    #pragma unroll 8
    for (int k = 0; k < 256; k++) d += sR[k] * wrow[k];
    float v = fmaxf(d + t2b[j], 0.f);

    red[j] = v; __syncthreads();
    for (int s = 64; s > 0; s >>= 1) {
        if (j < s) red[j] = fmaxf(red[j], red[j + s]);
        __syncthreads();
    }
    float m = red[0]; __syncthreads();
    float e = expf(v - m);
    red[j] = e; __syncthreads();
    for (int s = 64; s > 0; s >>= 1) {
        if (j < s) red[j] += red[j + s];
        __syncthreads();
    }
    float sum = red[0];
    g_attnT[((size_t)b * CC + j) * C2 + i] = e / sum;
}

// ================================================================ kernel 4
// out[c][n] = sum_d attnT[c][d] * vcon[n][d], fp16 single product.
// grid (256 ntiles, 8), block 256, 2 blocks/SM.
extern "C" __global__ void __launch_bounds__(256, 2)
k_out(float* __restrict__ out)
{
    extern __shared__ char smem[];
    u32 sb = smem_u32(smem);
    int tid = threadIdx.x, wid = tid >> 5, lane = tid & 31;
    int b = blockIdx.y, n0 = blockIdx.x * 128;
    const float* At = g_attnT + (size_t)b * CC * C2;
    const __half* V = g_vcon + (size_t)b * NN * C2;

    float acc[4][4][4];
    #pragma unroll
    for (int i = 0; i < 4; i++)
        #pragma unroll
        for (int j = 0; j < 4; j++)
            #pragma unroll
            for (int e = 0; e < 4; e++) acc[i][j][e] = 0.f;

    for (int ch = 0; ch < 2; ch++) {
        __syncthreads();
        int k0 = ch * 128;
        for (int it = tid; it < 128 * 32; it += 256) {
            int c = it >> 5, d4 = (it & 31) * 4;
            float4 v = *(const float4*)(At + (size_t)c * C2 + k0 + d4);
            *(u32*)(smem + A_HI + c * ST_B + d4 * 2)     = packh2(v.x, v.y);
            *(u32*)(smem + A_HI + c * ST_B + d4 * 2 + 4) = packh2(v.z, v.w);
        }
        for (int it = tid; it < 128 * 16; it += 256) {
            int n = it >> 4, seg = it & 15;
            *(uint4*)(smem + A_LO + n * ST_B + seg * 16) =
                *((const uint4*)(V + (size_t)(n0 + n) * C2 + k0) + seg);
        }
        __syncthreads();
        gemm1_f16(sb, A_HI, A_LO, acc, wid, lane);
    }

    int m0w = (wid >> 2) * 64, n0w = (wid & 3) * 32;
    int r = lane >> 2, cpo = (lane & 3) * 2;
    #pragma unroll
    for (int mi = 0; mi < 4; mi++) {
        int m = m0w + mi * 16 + r;
        #pragma unroll
        for (int ni = 0; ni < 4; ni++) {
            int n = n0w + ni * 8 + cpo;
            *(float2*)&out[((size_t)(b * CC + m)) * NN + n0 + n] =
                make_float2(acc[mi][ni][0], acc[mi][ni][1]);
            *(float2*)&out[((size_t)(b * CC + m + 8)) * NN + n0 + n] =
                make_float2(acc[mi][ni][2], acc[mi][ni][3]);
        }
    }
}

// ---------------------------------------------------------------- launch
extern "C" void kernel_launch(void* const* d_in, const int* in_sizes, int n_in,
                              void* d_out, int out_size)
{
    const float* x   = (const float*)d_in[0];
    const float* y   = (const float*)d_in[1];
    const float* qw  = (const float*)d_in[2];
    const float* qb  = (const float*)d_in[3];
    const float* kw  = (const float*)d_in[4];
    const float* kb  = (const float*)d_in[5];
    const float* v1w = (const float*)d_in[6];
    const float* v1b = (const float*)d_in[7];
    const float* v2w = (const float*)d_in[8];
    const float* v2b = (const float*)d_in[9];
    const float* t1w = (const float*)d_in[10];
    const float* t1b = (const float*)d_in[11];
    const float* t2w = (const float*)d_in[12];
    const float* t2b = (const float*)d_in[13];
    float* out = (float*)d_out;

    cudaFuncSetAttribute(k_pconv,  cudaFuncAttributeMaxDynamicSharedMemorySize, SM_PCONV);
    cudaFuncSetAttribute(k_energy, cudaFuncAttributeMaxDynamicSharedMemorySize, SM_4PL);
    cudaFuncSetAttribute(k_out,    cudaFuncAttributeMaxDynamicSharedMemorySize, SM_2PL);

    k_pconv <<<dim3(NN / 128, BB, 2), 256, SM_PCONV>>>(x, y, qw, qb, kw, kb,
                                                       v1w, v1b, v2w, v2b);
    k_energy<<<dim3(3 * SPE, BB), 256, SM_4PL>>>();
    k_ereduce<<<dim3(C2, BB), C2>>>();
    k_mlp1  <<<dim3(32, BB), 256>>>(t1w, t1b);
    k_mlp2  <<<dim3(C2, BB), CC>>>(t2w, t2b);
    k_out   <<<dim3(NN / 128, BB), 256, SM_2PL>>>(out);
}

// round 14
// speedup vs baseline: 2.8844x; 1.0859x over previous
#include <cuda_runtime.h>
#include <cuda_bf16.h>
#include <cuda_fp16.h>
#include <stdint.h>
#include <math.h>

#define BB 8
#define CC 128
#define C2 256
#define NN 32768
#define ESP 32            // energy K-splits
#define EK0 (NN / ESP)    // 1024 per split
#define ENCH (EK0 / 64)   // 16 chunks of 64

typedef unsigned int u32;
typedef unsigned long long u64;

// pconv plane geometry (K=128): [128 rows][136 halves], stride 272B
#define ST_B 272
#define A_HI 0
#define A_LO 34816
#define B_HI 69632
#define B_LO 104448
#define B_F16 139264
#define SM_PCONV (B_F16 + 34816 + 512)

// K=64 chunk plane geometry: [128 rows][72 halves], stride 144B
#define E_ST 144
#define E_PL 18432

__device__ __forceinline__ u32 smem_u32(const void* p) {
    u32 a;
    asm("{ .reg .u64 t; cvta.to.shared.u64 t, %1; cvt.u32.u64 %0, t; }"
        : "=r"(a) : "l"(p));
    return a;
}

#define LDSM4(r, addr) \
    asm volatile("ldmatrix.sync.aligned.m8n8.x4.shared.b16 {%0,%1,%2,%3}, [%4];" \
        : "=r"((r)[0]), "=r"((r)[1]), "=r"((r)[2]), "=r"((r)[3]) : "r"(addr))

#define MMA_BF(acc, a, b0, b1) \
    asm volatile("mma.sync.aligned.m16n8k16.row.col.f32.bf16.bf16.f32 " \
        "{%0,%1,%2,%3}, {%4,%5,%6,%7}, {%8,%9}, {%0,%1,%2,%3};" \
        : "+f"((acc)[0]), "+f"((acc)[1]), "+f"((acc)[2]), "+f"((acc)[3]) \
        : "r"((a)[0]), "r"((a)[1]), "r"((a)[2]), "r"((a)[3]), "r"(b0), "r"(b1))

#define MMA_FP(acc, a, b0, b1) \
    asm volatile("mma.sync.aligned.m16n8k16.row.col.f32.f16.f16.f32 " \
        "{%0,%1,%2,%3}, {%4,%5,%6,%7}, {%8,%9}, {%0,%1,%2,%3};" \
        : "+f"((acc)[0]), "+f"((acc)[1]), "+f"((acc)[2]), "+f"((acc)[3]) \
        : "r"((a)[0]), "r"((a)[1]), "r"((a)[2]), "r"((a)[3]), "r"(b0), "r"(b1))

#define CPA16(s, g) \
    asm volatile("cp.async.cg.shared.global [%0], [%1], 16;" \
        :: "r"(s), "l"(g) : "memory")
#define CP_COMMIT() asm volatile("cp.async.commit_group;" ::: "memory")
#define CP_WAIT1()  asm volatile("cp.async.wait_group 1;" ::: "memory")
#define CP_WAIT0()  asm volatile("cp.async.wait_group 0;" ::: "memory")

__device__ __forceinline__ u32 packh2(float a, float b) {
    __half2 h = __floats2half2_rn(a, b);
    return *(u32*)&h;
}
__device__ __forceinline__ u32 hilo2(float v0, float v1, u32& lopack) {
    __nv_bfloat16 h0 = __float2bfloat16_rn(v0);
    __nv_bfloat16 h1 = __float2bfloat16_rn(v1);
    __nv_bfloat16 l0 = __float2bfloat16_rn(v0 - __bfloat162float(h0));
    __nv_bfloat16 l1 = __float2bfloat16_rn(v1 - __bfloat162float(h1));
    lopack = (u32)__bfloat16_as_ushort(l0) | ((u32)__bfloat16_as_ushort(l1) << 16);
    return (u32)__bfloat16_as_ushort(h0) | ((u32)__bfloat16_as_ushort(h1) << 16);
}

// ---------------------------------------------------------------- scratch
__device__ __align__(16) __nv_bfloat16 g_xcon_hi[(size_t)BB * C2 * NN]; // [b][d][n]
__device__ __align__(16) __nv_bfloat16 g_xcon_lo[(size_t)BB * C2 * NN];
__device__ __align__(16) __half g_vcon[(size_t)BB * NN * C2];           // [b][n][d]
__device__ float g_epart[(size_t)BB * ESP * C2 * C2];                   // [b][s][i][j]
__device__ float g_energy[BB * C2 * C2];
__device__ float g_e1[BB * C2 * C2];
__device__ float g_attnT[BB * CC * C2];                                 // [b][c][d]

// ---------------------------------------------------------------- GEMM cores
// K=128, stride 272B (pconv)
__device__ __forceinline__ void gemm3_bf16(u32 sb, u32 ah_off, u32 al_off,
                                           u32 bh_off, u32 bl_off,
                                           float (&acc)[4][4][4],
                                           int wid, int lane)
{
    const int m0 = (wid >> 2) * 64, n0 = (wid & 3) * 32;
    const int row = lane & 15;
    const int half = (lane >> 4) * 16;
    #pragma unroll
    for (int ks = 0; ks < 8; ks++) {
        int kb = ks * 32 + half;
        u32 ah[4][4], al[4][4], bh[2][4], bl[2][4];
        #pragma unroll
        for (int mi = 0; mi < 4; mi++) {
            int ro = (m0 + mi * 16 + row) * ST_B + kb;
            LDSM4(ah[mi], sb + ah_off + ro);
            LDSM4(al[mi], sb + al_off + ro);
        }
        #pragma unroll
        for (int nb = 0; nb < 2; nb++) {
            int ro = (n0 + nb * 16 + row) * ST_B + kb;
            LDSM4(bh[nb], sb + bh_off + ro);
            LDSM4(bl[nb], sb + bl_off + ro);
        }
        #pragma unroll
        for (int mi = 0; mi < 4; mi++)
            #pragma unroll
            for (int ni = 0; ni < 4; ni++) {
                int nb = ni >> 1, sel = ni & 1;
                MMA_BF(acc[mi][ni], ah[mi], bh[nb][sel], bh[nb][sel + 2]);
                MMA_BF(acc[mi][ni], al[mi], bh[nb][sel], bh[nb][sel + 2]);
                MMA_BF(acc[mi][ni], ah[mi], bl[nb][sel], bl[nb][sel + 2]);
            }
    }
}

__device__ __forceinline__ void gemm1_f16(u32 sb, u32 a_off, u32 b_off,
                                          float (&acc)[4][4][4],
                                          int wid, int lane)
{
    const int m0 = (wid >> 2) * 64, n0 = (wid & 3) * 32;
    const int row = lane & 15;
    const int half = (lane >> 4) * 16;
    #pragma unroll
    for (int ks = 0; ks < 8; ks++) {
        int kb = ks * 32 + half;
        u32 ah[4][4], bh[2][4];
        #pragma unroll
        for (int mi = 0; mi < 4; mi++)
            LDSM4(ah[mi], sb + a_off + (m0 + mi * 16 + row) * ST_B + kb);
        #pragma unroll
        for (int nb = 0; nb < 2; nb++)
            LDSM4(bh[nb], sb + b_off + (n0 + nb * 16 + row) * ST_B + kb);
        #pragma unroll
        for (int mi = 0; mi < 4; mi++)
            #pragma unroll
            for (int ni = 0; ni < 4; ni++) {
                int nb = ni >> 1, sel = ni & 1;
                MMA_FP(acc[mi][ni], ah[mi], bh[nb][sel], bh[nb][sel + 2]);
            }
    }
}

// K=64 chunk, stride 144B (energy / out)
__device__ __forceinline__ void gemm3_k64(u32 sb, u32 ah_off, u32 al_off,
                                          u32 bh_off, u32 bl_off,
                                          float (&acc)[4][4][4],
                                          int wid, int lane)
{
    const int m0 = (wid >> 2) * 64, n0 = (wid & 3) * 32;
    const int row = lane & 15;
    const int half = (lane >> 4) * 16;
    #pragma unroll
    for (int ks = 0; ks < 4; ks++) {
        int kb = ks * 32 + half;
        u32 ah[4][4], al[4][4], bh[2][4], bl[2][4];
        #pragma unroll
        for (int mi = 0; mi < 4; mi++) {
            int ro = (m0 + mi * 16 + row) * E_ST + kb;
            LDSM4(ah[mi], sb + ah_off + ro);
            LDSM4(al[mi], sb + al_off + ro);
        }
        #pragma unroll
        for (int nb = 0; nb < 2; nb++) {
            int ro = (n0 + nb * 16 + row) * E_ST + kb;
            LDSM4(bh[nb], sb + bh_off + ro);
            LDSM4(bl[nb], sb + bl_off + ro);
        }
        #pragma unroll
        for (int mi = 0; mi < 4; mi++)
            #pragma unroll
            for (int ni = 0; ni < 4; ni++) {
                int nb = ni >> 1, sel = ni & 1;
                MMA_BF(acc[mi][ni], ah[mi], bh[nb][sel], bh[nb][sel + 2]);
                MMA_BF(acc[mi][ni], al[mi], bh[nb][sel], bh[nb][sel + 2]);
                MMA_BF(acc[mi][ni], ah[mi], bl[nb][sel], bl[nb][sel + 2]);
            }
    }
}

__device__ __forceinline__ void gemm1_k64(u32 sb, u32 a_off, u32 b_off,
                                          float (&acc)[4][4][4],
                                          int wid, int lane)
{
    const int m0 = (wid >> 2) * 64, n0 = (wid & 3) * 32;
    const int row = lane & 15;
    const int half = (lane >> 4) * 16;
    #pragma unroll
    for (int ks = 0; ks < 4; ks++) {
        int kb = ks * 32 + half;
        u32 ah[4][4], bh[2][4];
        #pragma unroll
        for (int mi = 0; mi < 4; mi++)
            LDSM4(ah[mi], sb + a_off + (m0 + mi * 16 + row) * E_ST + kb);
        #pragma unroll
        for (int nb = 0; nb < 2; nb++)
            LDSM4(bh[nb], sb + b_off + (n0 + nb * 16 + row) * E_ST + kb);
        #pragma unroll
        for (int mi = 0; mi < 4; mi++)
            #pragma unroll
            for (int ni = 0; ni < 4; ni++) {
                int nb = ni >> 1, sel = ni & 1;
                MMA_FP(acc[mi][ni], ah[mi], bh[nb][sel], bh[nb][sel + 2]);
            }
    }
}

// ================================================================ kernel 1
// (unchanged from R12 champion)
extern "C" __global__ void __launch_bounds__(256, 1)
k_pconv(const float* __restrict__ x, const float* __restrict__ y,
        const float* __restrict__ qw, const float* __restrict__ qb,
        const float* __restrict__ kw, const float* __restrict__ kb,
        const float* __restrict__ v1w, const float* __restrict__ v1b,
        const float* __restrict__ v2w, const float* __restrict__ v2b)
{
    extern __shared__ char smem[];
    u32 sb = smem_u32(smem);
    int tid = threadIdx.x, wid = tid >> 5, lane = tid & 31;
    int b = blockIdx.y, n0 = blockIdx.x * 128, src = blockIdx.z;
    const float* In = (src ? y : x) + (size_t)b * CC * NN;
    int zoff = src ? 0 : 128;
    float* bias_s = (float*)(smem + SM_PCONV - 512);

    for (int it = tid; it < 128 * 32; it += 256) {
        int c = it >> 5, j = it & 31;
        #pragma unroll
        for (int q = 0; q < 4; q++) {
            int n = j + q * 32;
            float v = In[(size_t)c * NN + n0 + n];
            __nv_bfloat16 h = __float2bfloat16_rn(v);
            __nv_bfloat16 l = __float2bfloat16_rn(v - __bfloat162float(h));
            *(__nv_bfloat16*)(smem + B_HI + n * ST_B + c * 2) = h;
            *(__nv_bfloat16*)(smem + B_LO + n * ST_B + c * 2) = l;
            *(__half*)(smem + B_F16 + n * ST_B + c * 2) = __float2half_rn(v);
        }
    }

    for (int zi = 0; zi < 2; zi++) {
        const float* W; const float* bsrc;
        if (src == 0) { W = zi ? v1w : kw; bsrc = zi ? v1b : kb; }
        else          { W = zi ? v2w : qw; bsrc = zi ? v2b : qb; }
        __syncthreads();
        if (zi == 0) {
            for (int it = tid; it < 128 * 32; it += 256) {
                int o = it >> 5, c4 = (it & 31) * 4;
                float4 v = *(const float4*)(W + o * 128 + c4);
                u32 l01, h01 = hilo2(v.x, v.y, l01);
                u32 l23, h23 = hilo2(v.z, v.w, l23);
                *(u32*)(smem + A_HI + o * ST_B + c4 * 2)     = h01;
                *(u32*)(smem + A_HI + o * ST_B + c4 * 2 + 4) = h23;
                *(u32*)(smem + A_LO + o * ST_B + c4 * 2)     = l01;
                *(u32*)(smem + A_LO + o * ST_B + c4 * 2 + 4) = l23;
            }
        } else {
            for (int it = tid; it < 128 * 32; it += 256) {
                int o = it >> 5, c4 = (it & 31) * 4;
                float4 v = *(const float4*)(W + o * 128 + c4);
                *(u32*)(smem + A_HI + o * ST_B + c4 * 2)     = packh2(v.x, v.y);
                *(u32*)(smem + A_HI + o * ST_B + c4 * 2 + 4) = packh2(v.z, v.w);
            }
        }
        if (tid < 128) bias_s[tid] = bsrc[tid];
        __syncthreads();

        float acc[4][4][4];
        #pragma unroll
        for (int i = 0; i < 4; i++)
            #pragma unroll
            for (int j = 0; j < 4; j++)
                #pragma unroll
                for (int e = 0; e < 4; e++) acc[i][j][e] = 0.f;

        if (zi == 0) gemm3_bf16(sb, A_HI, A_LO, B_HI, B_LO, acc, wid, lane);
        else         gemm1_f16(sb, A_HI, B_F16, acc, wid, lane);

        int m0w = (wid >> 2) * 64, n0w = (wid & 3) * 32;
        int r = lane >> 2, cpo = (lane & 3) * 2;

        if (zi == 0) {
            #pragma unroll
            for (int mi = 0; mi < 4; mi++) {
                int o = m0w + mi * 16 + r;
                float bb0 = bias_s[o], bb8 = bias_s[o + 8];
                #pragma unroll
                for (int ni = 0; ni < 4; ni++) {
                    int n = n0w + ni * 8 + cpo;
                    u32 lp, hp;
                    hp = hilo2(acc[mi][ni][0] + bb0, acc[mi][ni][1] + bb0, lp);
                    size_t gi = ((size_t)(b * C2 + zoff + o)) * NN + n0 + n;
                    *(u32*)&g_xcon_hi[gi] = hp;
                    *(u32*)&g_xcon_lo[gi] = lp;
                    hp = hilo2(acc[mi][ni][2] + bb8, acc[mi][ni][3] + bb8, lp);
                    gi = ((size_t)(b * C2 + zoff + o + 8)) * NN + n0 + n;
                    *(u32*)&g_xcon_hi[gi] = hp;
                    *(u32*)&g_xcon_lo[gi] = lp;
                }
            }
        } else {
            __syncthreads();
            #pragma unroll
            for (int mi = 0; mi < 4; mi++) {
                int o = m0w + mi * 16 + r;
                float bb0 = bias_s[o], bb8 = bias_s[o + 8];
                #pragma unroll
                for (int ni = 0; ni < 4; ni++) {
                    int n = n0w + ni * 8 + cpo;
                    #pragma unroll
                    for (int e = 0; e < 4; e++) {
                        float v = acc[mi][ni][e] + ((e >= 2) ? bb8 : bb0);
                        int oo = o + ((e >= 2) ? 8 : 0);
                        int nn = n + (e & 1);
                        *(__half*)(smem + A_HI + nn * ST_B + oo * 2) =
                            __float2half_rn(v);
                    }
                }
            }
            __syncthreads();
            for (int it = tid; it < 128 * 64; it += 256) {
                int n = it >> 6, w = it & 63;
                u32 val = *(u32*)(smem + A_HI + n * ST_B + w * 4);
                *((u32*)(g_vcon + ((size_t)(b * NN + n0 + n)) * C2 + zoff) + w) = val;
            }
        }
    }
}

// ================================================================ kernel 2a
// energy DIAG Gram tiles (A aliases B): grid (2*ESP, 8), cp.async pipelined.
extern "C" __global__ void __launch_bounds__(256, 2)
k_energy_diag()
{
    extern __shared__ char smem[];
    u32 sb = smem_u32(smem);
    int tid = threadIdx.x, wid = tid >> 5, lane = tid & 31;
    int b = blockIdx.y;
    int t = blockIdx.x >> 5, sp = blockIdx.x & 31;
    int i0 = t * 128;
    const __nv_bfloat16* Xh = g_xcon_hi + (size_t)b * C2 * NN;
    const __nv_bfloat16* Xl = g_xcon_lo + (size_t)b * C2 * NN;
    int k0 = sp * EK0;

    float acc[4][4][4];
    #pragma unroll
    for (int i = 0; i < 4; i++)
        #pragma unroll
        for (int j = 0; j < 4; j++)
            #pragma unroll
            for (int e = 0; e < 4; e++) acc[i][j][e] = 0.f;

    auto issue = [&](int ch, int buf) {
        int kb = k0 + ch * 64;
        for (int it = tid; it < 2048; it += 256) {
            int pl = it >> 10, r = (it >> 3) & 127, seg = it & 7;
            const __nv_bfloat16* src =
                (pl ? Xl : Xh) + (size_t)(i0 + r) * NN + kb + seg * 8;
            CPA16(sb + buf * 36864 + pl * E_PL + r * E_ST + seg * 16, src);
        }
        CP_COMMIT();
    };

    issue(0, 0);
    for (int ch = 0; ch < ENCH; ch++) {
        int buf = ch & 1;
        if (ch + 1 < ENCH) { issue(ch + 1, (ch + 1) & 1); CP_WAIT1(); }
        else               { CP_WAIT0(); }
        __syncthreads();
        u32 base = buf * 36864;
        gemm3_k64(sb, base, base + E_PL, base, base + E_PL, acc, wid, lane);
        __syncthreads();
    }

    int m0w = (wid >> 2) * 64, n0w = (wid & 3) * 32;
    int r = lane >> 2, cpo = (lane & 3) * 2;
    float* Ep = g_epart + ((size_t)(b * ESP + sp)) * C2 * C2;
    #pragma unroll
    for (int mi = 0; mi < 4; mi++) {
        int i = i0 + m0w + mi * 16 + r;
        #pragma unroll
        for (int ni = 0; ni < 4; ni++) {
            int j = i0 + n0w + ni * 8 + cpo;
            *(float2*)&Ep[(size_t)i * C2 + j] =
                make_float2(acc[mi][ni][0], acc[mi][ni][1]);
            *(float2*)&Ep[(size_t)(i + 8) * C2 + j] =
                make_float2(acc[mi][ni][2], acc[mi][ni][3]);
        }
    }
}

// ================================================================ kernel 2b
// energy OFF-DIAG tile (rows 0..127 x cols 128..255): grid (ESP, 8).
extern "C" __global__ void __launch_bounds__(256, 1)
k_energy_off()
{
    extern __shared__ char smem[];
    u32 sb = smem_u32(smem);
    int tid = threadIdx.x, wid = tid >> 5, lane = tid & 31;
    int b = blockIdx.y, sp = blockIdx.x;
    const __nv_bfloat16* Xh = g_xcon_hi + (size_t)b * C2 * NN;
    const __nv_bfloat16* Xl = g_xcon_lo + (size_t)b * C2 * NN;
    int k0 = sp * EK0;

    float acc[4][4][4];
    #pragma unroll
    for (int i = 0; i < 4; i++)
        #pragma unroll
        for (int j = 0; j < 4; j++)
            #pragma unroll
            for (int e = 0; e < 4; e++) acc[i][j][e] = 0.f;

    // planes per buf: {R_hi, R_lo, C_hi, C_lo}
    auto issue = [&](int ch, int buf) {
        int kb = k0 + ch * 64;
        for (int it = tid; it < 4096; it += 256) {
            int pl = it >> 10, r = (it >> 3) & 127, seg = it & 7;
            int rowb = (pl >= 2) ? 128 : 0;
            const __nv_bfloat16* src =
                ((pl & 1) ? Xl : Xh) + (size_t)(rowb + r) * NN + kb + seg * 8;
            CPA16(sb + buf * 73728 + pl * E_PL + r * E_ST + seg * 16, src);
        }
        CP_COMMIT();
    };

    issue(0, 0);
    for (int ch = 0; ch < ENCH; ch++) {
        int buf = ch & 1;
        if (ch + 1 < ENCH) { issue(ch + 1, (ch + 1) & 1); CP_WAIT1(); }
        else               { CP_WAIT0(); }
        __syncthreads();
        u32 base = buf * 73728;
        gemm3_k64(sb, base, base + E_PL, base + 2 * E_PL, base + 3 * E_PL,
                  acc, wid, lane);
        __syncthreads();
    }

    int m0w = (wid >> 2) * 64, n0w = (wid & 3) * 32;
    int r = lane >> 2, cpo = (lane & 3) * 2;
    float* Ep = g_epart + ((size_t)(b * ESP + sp)) * C2 * C2;
    #pragma unroll
    for (int mi = 0; mi < 4; mi++) {
        int i = m0w + mi * 16 + r;
        #pragma unroll
        for (int ni = 0; ni < 4; ni++) {
            int j = 128 + n0w + ni * 8 + cpo;
            *(float2*)&Ep[(size_t)i * C2 + j] =
                make_float2(acc[mi][ni][0], acc[mi][ni][1]);
            *(float2*)&Ep[(size_t)(i + 8) * C2 + j] =
                make_float2(acc[mi][ni][2], acc[mi][ni][3]);
        }
    }
}

// ================================================================ kernel 2c
extern "C" __global__ void k_ereduce()
{
    int j = threadIdx.x, i = blockIdx.x, b = blockIdx.y;
    int si = i, sj = j;
    if (i >= 128 && j < 128) { si = j; sj = i; }
    size_t base = ((size_t)(b * ESP) * C2 + si) * C2 + sj;
    float s = 0.f;
    #pragma unroll
    for (int sp = 0; sp < ESP; sp++) s += g_epart[base + (size_t)sp * C2 * C2];
    g_energy[((size_t)b * C2 + i) * C2 + j] = s * (1.0f / 16.0f);
}

// ================================================================ kernel 3a
typedef unsigned long long ull;
__device__ __forceinline__ void fma2(ull& acc, ull a, ull b) {
    asm("fma.rn.f32x2 %0, %1, %2, %0;" : "+l"(acc) : "l"(a), "l"(b));
}
__device__ __forceinline__ void unpack2(float& lo, float& hi, ull p) {
    asm("mov.b64 {%0, %1}, %2;" : "=f"(lo), "=f"(hi) : "l"(p));
}

extern "C" __global__ void __launch_bounds__(256)
k_mlp1(const float* __restrict__ t1w, const float* __restrict__ t1b)
{
    __shared__ float sE[8 * 256];
    int b = blockIdx.y, rg = blockIdx.x;
    int tid = threadIdx.x;
    const float* E = g_energy + (size_t)b * C2 * C2 + (size_t)rg * 8 * C2;
    #pragma unroll
    for (int t = 0; t < 8; t++) sE[tid + t * 256] = E[tid + t * 256];
    __syncthreads();

    int j = tid;
    ull acc2[8];
    #pragma unroll
    for (int i = 0; i < 8; i++) acc2[i] = 0ull;
    const ull* wrow = (const ull*)(t1w + (size_t)j * C2);
    #pragma unroll 4
    for (int k2 = 0; k2 < 128; k2++) {
        ull w = wrow[k2];
        #pragma unroll
        for (int i = 0; i < 8; i++) {
            ull e = ((const ull*)(sE + i * 256))[k2];
            fma2(acc2[i], e, w);
        }
    }
    float bv = t1b[j];
    float* O = g_e1 + (size_t)b * C2 * C2 + (size_t)rg * 8 * C2;
    #pragma unroll
    for (int i = 0; i < 8; i++) {
        float lo, hi;
        unpack2(lo, hi, acc2[i]);
        O[i * 256 + j] = fmaxf(lo + hi + bv, 0.f);
    }
}

// ================================================================ kernel 3b
extern "C" __global__ void __launch_bounds__(128)
k_mlp2(const float* __restrict__ t2w, const float* __restrict__ t2b)
{
    __shared__ float sR[256];
    __shared__ float red[128];
    int b = blockIdx.y, i = blockIdx.x, j = threadIdx.x;
    const float* E1 = g_e1 + ((size_t)b * C2 + i) * C2;
    sR[j] = E1[j];
    sR[j + 128] = E1[j + 128];
    __syncthreads();

    const float* wrow = t2w + (size_t)j * C2;
    float d = 0.f;
    #pragma unroll 8
    for (int k = 0; k < 256; k++) d += sR[k] * wrow[k];
    float v = fmaxf(d + t2b[j], 0.f);

    red[j] = v; __syncthreads();
    for (int s = 64; s > 0; s >>= 1) {
        if (j < s) red[j] = fmaxf(red[j], red[j + s]);
        __syncthreads();
    }
    float m = red[0]; __syncthreads();
    float e = expf(v - m);
    red[j] = e; __syncthreads();
    for (int s = 64; s > 0; s >>= 1) {
        if (j < s) red[j] += red[j + s];
        __syncthreads();
    }
    float sum = red[0];
    g_attnT[((size_t)b * CC + j) * C2 + i] = e / sum;
}

// ================================================================ kernel 4
// out[c][n] = sum_d attnT[c][d] * vcon[n][d]; K=64 chunks, cp.async pipelined.
// planes per buf: {A(attnT fp16), V} @ stride 144B. grid (256 ntiles, 8).
extern "C" __global__ void __launch_bounds__(256, 2)
k_out(float* __restrict__ out)
{
    extern __shared__ char smem[];
    u32 sb = smem_u32(smem);
    int tid = threadIdx.x, wid = tid >> 5, lane = tid & 31;
    int b = blockIdx.y, n0 = blockIdx.x * 128;
    const float* At = g_attnT + (size_t)b * CC * C2;
    const __half* V = g_vcon + (size_t)b * NN * C2;

    float acc[4][4][4];
    #pragma unroll
    for (int i = 0; i < 4; i++)
        #pragma unroll
        for (int j = 0; j < 4; j++)
            #pragma unroll
            for (int e = 0; e < 4; e++) acc[i][j][e] = 0.f;

    // A fill: GENERIC stores via smem pointer (bug fix vs R13 — sb is only
    // valid for ldmatrix/cp.async operands, never generic dereference).
    auto fill = [&](int ch, int buf) {
        int d0 = ch * 64;
        char* gb = smem + buf * 36864;
        u32 sbb = sb + buf * 36864;
        for (int it = tid; it < 128 * 32; it += 256) {
            int c = it >> 5, p = it & 31;
            float2 v = *(const float2*)(At + (size_t)c * C2 + d0 + p * 2);
            *(u32*)(gb + c * E_ST + p * 4) = packh2(v.x, v.y);
        }
        for (int it = tid; it < 1024; it += 256) {
            int n = it >> 3, seg = it & 7;
            CPA16(sbb + E_PL + n * E_ST + seg * 16,
                  V + (size_t)(n0 + n) * C2 + d0 + seg * 8);
        }
        CP_COMMIT();
    };

    fill(0, 0);
    for (int ch = 0; ch < 4; ch++) {
        int buf = ch & 1;
        if (ch + 1 < 4) { fill(ch + 1, (ch + 1) & 1); CP_WAIT1(); }
        else            { CP_WAIT0(); }
        __syncthreads();
        u32 base = buf * 36864;
        gemm1_k64(sb, base, base + E_PL, acc, wid, lane);
        __syncthreads();
    }

    int m0w = (wid >> 2) * 64, n0w = (wid & 3) * 32;
    int r = lane >> 2, cpo = (lane & 3) * 2;
    #pragma unroll
    for (int mi = 0; mi < 4; mi++) {
        int m = m0w + mi * 16 + r;
        #pragma unroll
        for (int ni = 0; ni < 4; ni++) {
            int n = n0w + ni * 8 + cpo;
            *(float2*)&out[((size_t)(b * CC + m)) * NN + n0 + n] =
                make_float2(acc[mi][ni][0], acc[mi][ni][1]);
            *(float2*)&out[((size_t)(b * CC + m + 8)) * NN + n0 + n] =
                make_float2(acc[mi][ni][2], acc[mi][ni][3]);
        }
    }
}

// ---------------------------------------------------------------- launch
extern "C" void kernel_launch(void* const* d_in, const int* in_sizes, int n_in,
                              void* d_out, int out_size)
{
    const float* x   = (const float*)d_in[0];
    const float* y   = (const float*)d_in[1];
    const float* qw  = (const float*)d_in[2];
    const float* qb  = (const float*)d_in[3];
    const float* kw  = (const float*)d_in[4];
    const float* kb  = (const float*)d_in[5];
    const float* v1w = (const float*)d_in[6];
    const float* v1b = (const float*)d_in[7];
    const float* v2w = (const float*)d_in[8];
    const float* v2b = (const float*)d_in[9];
    const float* t1w = (const float*)d_in[10];
    const float* t1b = (const float*)d_in[11];
    const float* t2w = (const float*)d_in[12];
    const float* t2b = (const float*)d_in[13];
    float* out = (float*)d_out;

    cudaFuncSetAttribute(k_pconv,       cudaFuncAttributeMaxDynamicSharedMemorySize, SM_PCONV);
    cudaFuncSetAttribute(k_energy_diag, cudaFuncAttributeMaxDynamicSharedMemorySize, 73728);
    cudaFuncSetAttribute(k_energy_off,  cudaFuncAttributeMaxDynamicSharedMemorySize, 147456);
    cudaFuncSetAttribute(k_out,         cudaFuncAttributeMaxDynamicSharedMemorySize, 73728);

    k_pconv      <<<dim3(NN / 128, BB, 2), 256, SM_PCONV>>>(x, y, qw, qb, kw, kb,
                                                            v1w, v1b, v2w, v2b);
    k_energy_diag<<<dim3(2 * ESP, BB), 256, 73728>>>();
    k_energy_off <<<dim3(ESP, BB), 256, 147456>>>();
    k_ereduce    <<<dim3(C2, BB), C2>>>();
    k_mlp1       <<<dim3(32, BB), 256>>>(t1w, t1b);
    k_mlp2       <<<dim3(C2, BB), CC>>>(t2w, t2b);
    k_out        <<<dim3(NN / 128, BB), 256, 73728>>>(out);
}

// round 15
// speedup vs baseline: 3.5106x; 1.2171x over previous
#include <cuda_runtime.h>
#include <cuda_bf16.h>
#include <cuda_fp16.h>
#include <stdint.h>
#include <math.h>

#define BB 8
#define CC 128
#define C2 256
#define NN 32768
#define ESP 32            // epart slot stride (max splits)
#define ESPD 16           // diag splits
#define ESPO 32           // off-diag splits

typedef unsigned int u32;
typedef unsigned long long u64;

// pconv plane geometry (K=128): [128 rows][136 halves], stride 272B
#define ST_B 272
#define A_HI 0
#define A_LO 34816
#define B_HI 69632
#define B_LO 104448
#define B_F16 139264
#define SM_PCONV (B_F16 + 34816 + 512)

// K=64 chunk plane geometry: [128 rows][72 halves], stride 144B
#define E_ST 144
#define E_PL 18432
// K=32 chunk plane geometry (off-diag): [256 rows][40 halves], stride 80B
#define O_ST 80
#define O_PL 20480
#define O_BUF 40960

__device__ __forceinline__ u32 smem_u32(const void* p) {
    u32 a;
    asm("{ .reg .u64 t; cvta.to.shared.u64 t, %1; cvt.u32.u64 %0, t; }"
        : "=r"(a) : "l"(p));
    return a;
}

#define LDSM4(r, addr) \
    asm volatile("ldmatrix.sync.aligned.m8n8.x4.shared.b16 {%0,%1,%2,%3}, [%4];" \
        : "=r"((r)[0]), "=r"((r)[1]), "=r"((r)[2]), "=r"((r)[3]) : "r"(addr))

#define MMA_BF(acc, a, b0, b1) \
    asm volatile("mma.sync.aligned.m16n8k16.row.col.f32.bf16.bf16.f32 " \
        "{%0,%1,%2,%3}, {%4,%5,%6,%7}, {%8,%9}, {%0,%1,%2,%3};" \
        : "+f"((acc)[0]), "+f"((acc)[1]), "+f"((acc)[2]), "+f"((acc)[3]) \
        : "r"((a)[0]), "r"((a)[1]), "r"((a)[2]), "r"((a)[3]), "r"(b0), "r"(b1))

#define MMA_FP(acc, a, b0, b1) \
    asm volatile("mma.sync.aligned.m16n8k16.row.col.f32.f16.f16.f32 " \
        "{%0,%1,%2,%3}, {%4,%5,%6,%7}, {%8,%9}, {%0,%1,%2,%3};" \
        : "+f"((acc)[0]), "+f"((acc)[1]), "+f"((acc)[2]), "+f"((acc)[3]) \
        : "r"((a)[0]), "r"((a)[1]), "r"((a)[2]), "r"((a)[3]), "r"(b0), "r"(b1))

#define CPA16(s, g) \
    asm volatile("cp.async.cg.shared.global [%0], [%1], 16;" \
        :: "r"(s), "l"(g) : "memory")
#define CP_COMMIT() asm volatile("cp.async.commit_group;" ::: "memory")
#define CP_WAIT1()  asm volatile("cp.async.wait_group 1;" ::: "memory")
#define CP_WAIT0()  asm volatile("cp.async.wait_group 0;" ::: "memory")

__device__ __forceinline__ u32 packh2(float a, float b) {
    __half2 h = __floats2half2_rn(a, b);
    return *(u32*)&h;
}
__device__ __forceinline__ u32 hilo2(float v0, float v1, u32& lopack) {
    __nv_bfloat16 h0 = __float2bfloat16_rn(v0);
    __nv_bfloat16 h1 = __float2bfloat16_rn(v1);
    __nv_bfloat16 l0 = __float2bfloat16_rn(v0 - __bfloat162float(h0));
    __nv_bfloat16 l1 = __float2bfloat16_rn(v1 - __bfloat162float(h1));
    lopack = (u32)__bfloat16_as_ushort(l0) | ((u32)__bfloat16_as_ushort(l1) << 16);
    return (u32)__bfloat16_as_ushort(h0) | ((u32)__bfloat16_as_ushort(h1) << 16);
}

// ---------------------------------------------------------------- scratch
__device__ __align__(16) __nv_bfloat16 g_xcon_hi[(size_t)BB * C2 * NN]; // [b][d][n]
__device__ __align__(16) __nv_bfloat16 g_xcon_lo[(size_t)BB * C2 * NN];
__device__ __align__(16) __half g_vcon[(size_t)BB * NN * C2];           // [b][n][d]
__device__ float g_epart[(size_t)BB * ESP * C2 * C2];                   // [b][s][i][j]
__device__ float g_energy[BB * C2 * C2];
__device__ float g_e1[BB * C2 * C2];
__device__ __align__(16) __half g_attnT16[BB * CC * C2];                // [b][c][d]

// ---------------------------------------------------------------- GEMM cores
// K=128, stride 272B (pconv)
__device__ __forceinline__ void gemm3_bf16(u32 sb, u32 ah_off, u32 al_off,
                                           u32 bh_off, u32 bl_off,
                                           float (&acc)[4][4][4],
                                           int wid, int lane)
{
    const int m0 = (wid >> 2) * 64, n0 = (wid & 3) * 32;
    const int row = lane & 15;
    const int half = (lane >> 4) * 16;
    #pragma unroll
    for (int ks = 0; ks < 8; ks++) {
        int kb = ks * 32 + half;
        u32 ah[4][4], al[4][4], bh[2][4], bl[2][4];
        #pragma unroll
        for (int mi = 0; mi < 4; mi++) {
            int ro = (m0 + mi * 16 + row) * ST_B + kb;
            LDSM4(ah[mi], sb + ah_off + ro);
            LDSM4(al[mi], sb + al_off + ro);
        }
        #pragma unroll
        for (int nb = 0; nb < 2; nb++) {
            int ro = (n0 + nb * 16 + row) * ST_B + kb;
            LDSM4(bh[nb], sb + bh_off + ro);
            LDSM4(bl[nb], sb + bl_off + ro);
        }
        #pragma unroll
        for (int mi = 0; mi < 4; mi++)
            #pragma unroll
            for (int ni = 0; ni < 4; ni++) {
                int nb = ni >> 1, sel = ni & 1;
                MMA_BF(acc[mi][ni], ah[mi], bh[nb][sel], bh[nb][sel + 2]);
                MMA_BF(acc[mi][ni], al[mi], bh[nb][sel], bh[nb][sel + 2]);
                MMA_BF(acc[mi][ni], ah[mi], bl[nb][sel], bl[nb][sel + 2]);
            }
    }
}

__device__ __forceinline__ void gemm1_f16(u32 sb, u32 a_off, u32 b_off,
                                          float (&acc)[4][4][4],
                                          int wid, int lane)
{
    const int m0 = (wid >> 2) * 64, n0 = (wid & 3) * 32;
    const int row = lane & 15;
    const int half = (lane >> 4) * 16;
    #pragma unroll
    for (int ks = 0; ks < 8; ks++) {
        int kb = ks * 32 + half;
        u32 ah[4][4], bh[2][4];
        #pragma unroll
        for (int mi = 0; mi < 4; mi++)
            LDSM4(ah[mi], sb + a_off + (m0 + mi * 16 + row) * ST_B + kb);
        #pragma unroll
        for (int nb = 0; nb < 2; nb++)
            LDSM4(bh[nb], sb + b_off + (n0 + nb * 16 + row) * ST_B + kb);
        #pragma unroll
        for (int mi = 0; mi < 4; mi++)
            #pragma unroll
            for (int ni = 0; ni < 4; ni++) {
                int nb = ni >> 1, sel = ni & 1;
                MMA_FP(acc[mi][ni], ah[mi], bh[nb][sel], bh[nb][sel + 2]);
            }
    }
}

// K=64 chunk, stride 144B (diag / out)
__device__ __forceinline__ void gemm3_k64(u32 sb, u32 ah_off, u32 al_off,
                                          u32 bh_off, u32 bl_off,
                                          float (&acc)[4][4][4],
                                          int wid, int lane)
{
    const int m0 = (wid >> 2) * 64, n0 = (wid & 3) * 32;
    const int row = lane & 15;
    const int half = (lane >> 4) * 16;
    #pragma unroll
    for (int ks = 0; ks < 4; ks++) {
        int kb = ks * 32 + half;
        u32 ah[4][4], al[4][4], bh[2][4], bl[2][4];
        #pragma unroll
        for (int mi = 0; mi < 4; mi++) {
            int ro = (m0 + mi * 16 + row) * E_ST + kb;
            LDSM4(ah[mi], sb + ah_off + ro);
            LDSM4(al[mi], sb + al_off + ro);
        }
        #pragma unroll
        for (int nb = 0; nb < 2; nb++) {
            int ro = (n0 + nb * 16 + row) * E_ST + kb;
            LDSM4(bh[nb], sb + bh_off + ro);
            LDSM4(bl[nb], sb + bl_off + ro);
        }
        #pragma unroll
        for (int mi = 0; mi < 4; mi++)
            #pragma unroll
            for (int ni = 0; ni < 4; ni++) {
                int nb = ni >> 1, sel = ni & 1;
                MMA_BF(acc[mi][ni], ah[mi], bh[nb][sel], bh[nb][sel + 2]);
                MMA_BF(acc[mi][ni], al[mi], bh[nb][sel], bh[nb][sel + 2]);
                MMA_BF(acc[mi][ni], ah[mi], bl[nb][sel], bl[nb][sel + 2]);
            }
    }
}

__device__ __forceinline__ void gemm1_k64(u32 sb, u32 a_off, u32 b_off,
                                          float (&acc)[4][4][4],
                                          int wid, int lane)
{
    const int m0 = (wid >> 2) * 64, n0 = (wid & 3) * 32;
    const int row = lane & 15;
    const int half = (lane >> 4) * 16;
    #pragma unroll
    for (int ks = 0; ks < 4; ks++) {
        int kb = ks * 32 + half;
        u32 ah[4][4], bh[2][4];
        #pragma unroll
        for (int mi = 0; mi < 4; mi++)
            LDSM4(ah[mi], sb + a_off + (m0 + mi * 16 + row) * E_ST + kb);
        #pragma unroll
        for (int nb = 0; nb < 2; nb++)
            LDSM4(bh[nb], sb + b_off + (n0 + nb * 16 + row) * E_ST + kb);
        #pragma unroll
        for (int mi = 0; mi < 4; mi++)
            #pragma unroll
            for (int ni = 0; ni < 4; ni++) {
                int nb = ni >> 1, sel = ni & 1;
                MMA_FP(acc[mi][ni], ah[mi], bh[nb][sel], bh[nb][sel + 2]);
            }
    }
}

// K=32 chunk, stride 80B (off-diag)
__device__ __forceinline__ void gemm3_k32(u32 sb, u32 ah_off, u32 al_off,
                                          u32 bh_off, u32 bl_off,
                                          float (&acc)[4][4][4],
                                          int wid, int lane)
{
    const int m0 = (wid >> 2) * 64, n0 = (wid & 3) * 32;
    const int row = lane & 15;
    const int half = (lane >> 4) * 16;
    #pragma unroll
    for (int ks = 0; ks < 2; ks++) {
        int kb = ks * 32 + half;
        u32 ah[4][4], al[4][4], bh[2][4], bl[2][4];
        #pragma unroll
        for (int mi = 0; mi < 4; mi++) {
            int ro = (m0 + mi * 16 + row) * O_ST + kb;
            LDSM4(ah[mi], sb + ah_off + ro);
            LDSM4(al[mi], sb + al_off + ro);
        }
        #pragma unroll
        for (int nb = 0; nb < 2; nb++) {
            int ro = (n0 + nb * 16 + row) * O_ST + kb;
            LDSM4(bh[nb], sb + bh_off + ro);
            LDSM4(bl[nb], sb + bl_off + ro);
        }
        #pragma unroll
        for (int mi = 0; mi < 4; mi++)
            #pragma unroll
            for (int ni = 0; ni < 4; ni++) {
                int nb = ni >> 1, sel = ni & 1;
                MMA_BF(acc[mi][ni], ah[mi], bh[nb][sel], bh[nb][sel + 2]);
                MMA_BF(acc[mi][ni], al[mi], bh[nb][sel], bh[nb][sel + 2]);
                MMA_BF(acc[mi][ni], ah[mi], bl[nb][sel], bl[nb][sel + 2]);
            }
    }
}

// ================================================================ kernel 1
// (unchanged champion pconv)
extern "C" __global__ void __launch_bounds__(256, 1)
k_pconv(const float* __restrict__ x, const float* __restrict__ y,
        const float* __restrict__ qw, const float* __restrict__ qb,
        const float* __restrict__ kw, const float* __restrict__ kb,
        const float* __restrict__ v1w, const float* __restrict__ v1b,
        const float* __restrict__ v2w, const float* __restrict__ v2b)
{
    extern __shared__ char smem[];
    u32 sb = smem_u32(smem);
    int tid = threadIdx.x, wid = tid >> 5, lane = tid & 31;
    int b = blockIdx.y, n0 = blockIdx.x * 128, src = blockIdx.z;
    const float* In = (src ? y : x) + (size_t)b * CC * NN;
    int zoff = src ? 0 : 128;
    float* bias_s = (float*)(smem + SM_PCONV - 512);

    for (int it = tid; it < 128 * 32; it += 256) {
        int c = it >> 5, j = it & 31;
        #pragma unroll
        for (int q = 0; q < 4; q++) {
            int n = j + q * 32;
            float v = In[(size_t)c * NN + n0 + n];
            __nv_bfloat16 h = __float2bfloat16_rn(v);
            __nv_bfloat16 l = __float2bfloat16_rn(v - __bfloat162float(h));
            *(__nv_bfloat16*)(smem + B_HI + n * ST_B + c * 2) = h;
            *(__nv_bfloat16*)(smem + B_LO + n * ST_B + c * 2) = l;
            *(__half*)(smem + B_F16 + n * ST_B + c * 2) = __float2half_rn(v);
        }
    }

    for (int zi = 0; zi < 2; zi++) {
        const float* W; const float* bsrc;
        if (src == 0) { W = zi ? v1w : kw; bsrc = zi ? v1b : kb; }
        else          { W = zi ? v2w : qw; bsrc = zi ? v2b : qb; }
        __syncthreads();
        if (zi == 0) {
            for (int it = tid; it < 128 * 32; it += 256) {
                int o = it >> 5, c4 = (it & 31) * 4;
                float4 v = *(const float4*)(W + o * 128 + c4);
                u32 l01, h01 = hilo2(v.x, v.y, l01);
                u32 l23, h23 = hilo2(v.z, v.w, l23);
                *(u32*)(smem + A_HI + o * ST_B + c4 * 2)     = h01;
                *(u32*)(smem + A_HI + o * ST_B + c4 * 2 + 4) = h23;
                *(u32*)(smem + A_LO + o * ST_B + c4 * 2)     = l01;
                *(u32*)(smem + A_LO + o * ST_B + c4 * 2 + 4) = l23;
            }
        } else {
            for (int it = tid; it < 128 * 32; it += 256) {
                int o = it >> 5, c4 = (it & 31) * 4;
                float4 v = *(const float4*)(W + o * 128 + c4);
                *(u32*)(smem + A_HI + o * ST_B + c4 * 2)     = packh2(v.x, v.y);
                *(u32*)(smem + A_HI + o * ST_B + c4 * 2 + 4) = packh2(v.z, v.w);
            }
        }
        if (tid < 128) bias_s[tid] = bsrc[tid];
        __syncthreads();

        float acc[4][4][4];
        #pragma unroll
        for (int i = 0; i < 4; i++)
            #pragma unroll
            for (int j = 0; j < 4; j++)
                #pragma unroll
                for (int e = 0; e < 4; e++) acc[i][j][e] = 0.f;

        if (zi == 0) gemm3_bf16(sb, A_HI, A_LO, B_HI, B_LO, acc, wid, lane);
        else         gemm1_f16(sb, A_HI, B_F16, acc, wid, lane);

        int m0w = (wid >> 2) * 64, n0w = (wid & 3) * 32;
        int r = lane >> 2, cpo = (lane & 3) * 2;

        if (zi == 0) {
            #pragma unroll
            for (int mi = 0; mi < 4; mi++) {
                int o = m0w + mi * 16 + r;
                float bb0 = bias_s[o], bb8 = bias_s[o + 8];
                #pragma unroll
                for (int ni = 0; ni < 4; ni++) {
                    int n = n0w + ni * 8 + cpo;
                    u32 lp, hp;
                    hp = hilo2(acc[mi][ni][0] + bb0, acc[mi][ni][1] + bb0, lp);
                    size_t gi = ((size_t)(b * C2 + zoff + o)) * NN + n0 + n;
                    *(u32*)&g_xcon_hi[gi] = hp;
                    *(u32*)&g_xcon_lo[gi] = lp;
                    hp = hilo2(acc[mi][ni][2] + bb8, acc[mi][ni][3] + bb8, lp);
                    gi = ((size_t)(b * C2 + zoff + o + 8)) * NN + n0 + n;
                    *(u32*)&g_xcon_hi[gi] = hp;
                    *(u32*)&g_xcon_lo[gi] = lp;
                }
            }
        } else {
            __syncthreads();
            #pragma unroll
            for (int mi = 0; mi < 4; mi++) {
                int o = m0w + mi * 16 + r;
                float bb0 = bias_s[o], bb8 = bias_s[o + 8];
                #pragma unroll
                for (int ni = 0; ni < 4; ni++) {
                    int n = n0w + ni * 8 + cpo;
                    #pragma unroll
                    for (int e = 0; e < 4; e++) {
                        float v = acc[mi][ni][e] + ((e >= 2) ? bb8 : bb0);
                        int oo = o + ((e >= 2) ? 8 : 0);
                        int nn = n + (e & 1);
                        *(__half*)(smem + A_HI + nn * ST_B + oo * 2) =
                            __float2half_rn(v);
                    }
                }
            }
            __syncthreads();
            for (int it = tid; it < 128 * 64; it += 256) {
                int n = it >> 6, w = it & 63;
                u32 val = *(u32*)(smem + A_HI + n * ST_B + w * 4);
                *((u32*)(g_vcon + ((size_t)(b * NN + n0 + n)) * C2 + zoff) + w) = val;
            }
        }
    }
}

// ================================================================ kernel 2a
// energy DIAG Gram tiles: ESPD=16 splits, K=2048 per block (32 chunks of 64).
// grid (2*ESPD, 8), occ 2.
extern "C" __global__ void __launch_bounds__(256, 2)
k_energy_diag()
{
    extern __shared__ char smem[];
    u32 sb = smem_u32(smem);
    int tid = threadIdx.x, wid = tid >> 5, lane = tid & 31;
    int b = blockIdx.y;
    int t = blockIdx.x >> 4, sp = blockIdx.x & 15;
    int i0 = t * 128;
    const __nv_bfloat16* Xh = g_xcon_hi + (size_t)b * C2 * NN;
    const __nv_bfloat16* Xl = g_xcon_lo + (size_t)b * C2 * NN;
    int k0 = sp * 2048;

    float acc[4][4][4];
    #pragma unroll
    for (int i = 0; i < 4; i++)
        #pragma unroll
        for (int j = 0; j < 4; j++)
            #pragma unroll
            for (int e = 0; e < 4; e++) acc[i][j][e] = 0.f;

    auto issue = [&](int ch, int buf) {
        int kb = k0 + ch * 64;
        for (int it = tid; it < 2048; it += 256) {
            int pl = it >> 10, r = (it >> 3) & 127, seg = it & 7;
            const __nv_bfloat16* src =
                (pl ? Xl : Xh) + (size_t)(i0 + r) * NN + kb + seg * 8;
            CPA16(sb + buf * 36864 + pl * E_PL + r * E_ST + seg * 16, src);
        }
        CP_COMMIT();
    };

    issue(0, 0);
    for (int ch = 0; ch < 32; ch++) {
        int buf = ch & 1;
        if (ch + 1 < 32) { issue(ch + 1, (ch + 1) & 1); CP_WAIT1(); }
        else             { CP_WAIT0(); }
        __syncthreads();
        u32 base = buf * 36864;
        gemm3_k64(sb, base, base + E_PL, base, base + E_PL, acc, wid, lane);
        __syncthreads();
    }

    int m0w = (wid >> 2) * 64, n0w = (wid & 3) * 32;
    int r = lane >> 2, cpo = (lane & 3) * 2;
    float* Ep = g_epart + ((size_t)(b * ESP + sp)) * C2 * C2;
    #pragma unroll
    for (int mi = 0; mi < 4; mi++) {
        int i = i0 + m0w + mi * 16 + r;
        #pragma unroll
        for (int ni = 0; ni < 4; ni++) {
            int j = i0 + n0w + ni * 8 + cpo;
            *(float2*)&Ep[(size_t)i * C2 + j] =
                make_float2(acc[mi][ni][0], acc[mi][ni][1]);
            *(float2*)&Ep[(size_t)(i + 8) * C2 + j] =
                make_float2(acc[mi][ni][2], acc[mi][ni][3]);
        }
    }
}

// ================================================================ kernel 2b
// energy OFF-DIAG: ESPO=32 splits, K=32 chunks, one 256-row plane pair.
// A = rows 0..127, B = rows 128..255 of the same planes. occ 2.
extern "C" __global__ void __launch_bounds__(256, 2)
k_energy_off()
{
    extern __shared__ char smem[];
    u32 sb = smem_u32(smem);
    int tid = threadIdx.x, wid = tid >> 5, lane = tid & 31;
    int b = blockIdx.y, sp = blockIdx.x;
    const __nv_bfloat16* Xh = g_xcon_hi + (size_t)b * C2 * NN;
    const __nv_bfloat16* Xl = g_xcon_lo + (size_t)b * C2 * NN;
    int k0 = sp * 1024;

    float acc[4][4][4];
    #pragma unroll
    for (int i = 0; i < 4; i++)
        #pragma unroll
        for (int j = 0; j < 4; j++)
            #pragma unroll
            for (int e = 0; e < 4; e++) acc[i][j][e] = 0.f;

    auto issue = [&](int ch, int buf) {
        int kb = k0 + ch * 32;
        for (int it = tid; it < 2048; it += 256) {
            int pl = it >> 10, r = (it >> 2) & 255, seg = it & 3;
            const __nv_bfloat16* src =
                (pl ? Xl : Xh) + (size_t)r * NN + kb + seg * 8;
            CPA16(sb + buf * O_BUF + pl * O_PL + r * O_ST + seg * 16, src);
        }
        CP_COMMIT();
    };

    issue(0, 0);
    for (int ch = 0; ch < 32; ch++) {
        int buf = ch & 1;
        if (ch + 1 < 32) { issue(ch + 1, (ch + 1) & 1); CP_WAIT1(); }
        else             { CP_WAIT0(); }
        __syncthreads();
        u32 base = buf * O_BUF;
        gemm3_k32(sb, base, base + O_PL,
                  base + 128 * O_ST, base + O_PL + 128 * O_ST, acc, wid, lane);
        __syncthreads();
    }

    int m0w = (wid >> 2) * 64, n0w = (wid & 3) * 32;
    int r = lane >> 2, cpo = (lane & 3) * 2;
    float* Ep = g_epart + ((size_t)(b * ESP + sp)) * C2 * C2;
    #pragma unroll
    for (int mi = 0; mi < 4; mi++) {
        int i = m0w + mi * 16 + r;
        #pragma unroll
        for (int ni = 0; ni < 4; ni++) {
            int j = 128 + n0w + ni * 8 + cpo;
            *(float2*)&Ep[(size_t)i * C2 + j] =
                make_float2(acc[mi][ni][0], acc[mi][ni][1]);
            *(float2*)&Ep[(size_t)(i + 8) * C2 + j] =
                make_float2(acc[mi][ni][2], acc[mi][ni][3]);
        }
    }
}

// ================================================================ kernel 2c
// diag quadrants: 16 slots; mixed quadrants: 32 slots (mirrored).
extern "C" __global__ void k_ereduce()
{
    int j = threadIdx.x, i = blockIdx.x, b = blockIdx.y;
    bool offq = (i < 128) != (j < 128);
    int si = i, sj = j;
    if (i >= 128 && j < 128) { si = j; sj = i; }
    int ns = offq ? ESPO : ESPD;
    size_t base = ((size_t)(b * ESP) * C2 + si) * C2 + sj;
    float s = 0.f;
    for (int sp = 0; sp < ns; sp++) s += g_epart[base + (size_t)sp * C2 * C2];
    g_energy[((size_t)b * C2 + i) * C2 + j] = s * (1.0f / 16.0f);
}

// ================================================================ kernel 3a
// e1 = relu(energy @ t1w^T + b); smem-tiled coalesced t1w.
extern "C" __global__ void __launch_bounds__(256)
k_mlp1(const float* __restrict__ t1w, const float* __restrict__ t1b)
{
    __shared__ float sE[8 * 256];
    __shared__ float sW[256 * 33];
    int b = blockIdx.y, rg = blockIdx.x;
    int tid = threadIdx.x;
    const float* E = g_energy + (size_t)b * C2 * C2 + (size_t)rg * 8 * C2;
    #pragma unroll
    for (int t = 0; t < 8; t++) sE[t * 256 + tid] = E[t * 256 + tid];

    float acc[8];
    #pragma unroll
    for (int i = 0; i < 8; i++) acc[i] = 0.f;

    for (int kt = 0; kt < 8; kt++) {
        __syncthreads();
        for (int it = tid; it < 8192; it += 256) {
            int j = it >> 5, k = it & 31;
            sW[j * 33 + k] = t1w[(size_t)j * C2 + kt * 32 + k];
        }
        __syncthreads();
        #pragma unroll
        for (int k = 0; k < 32; k++) {
            float w = sW[tid * 33 + k];
            #pragma unroll
            for (int i = 0; i < 8; i++)
                acc[i] += sE[i * 256 + kt * 32 + k] * w;
        }
    }
    float bv = t1b[tid];
    float* O = g_e1 + (size_t)b * C2 * C2 + (size_t)rg * 8 * C2;
    #pragma unroll
    for (int i = 0; i < 8; i++)
        O[i * 256 + tid] = fmaxf(acc[i] + bv, 0.f);
}

// ================================================================ kernel 3b
// e2 + softmax, 8 rows/block, smem-tiled t2w; writes attnT as fp16.
extern "C" __global__ void __launch_bounds__(128)
k_mlp2(const float* __restrict__ t2w, const float* __restrict__ t2b)
{
    __shared__ float sR[8 * 256];
    __shared__ float sW2[128 * 33];
    __shared__ float red[128];
    int b = blockIdx.y, rg = blockIdx.x, j = threadIdx.x;
    const float* E1 = g_e1 + (size_t)b * C2 * C2 + (size_t)rg * 8 * C2;
    for (int it = j; it < 2048; it += 128) sR[it] = E1[it];

    float acc[8];
    #pragma unroll
    for (int i = 0; i < 8; i++) acc[i] = 0.f;

    for (int kt = 0; kt < 8; kt++) {
        __syncthreads();
        for (int it = j; it < 4096; it += 128) {
            int jj = it >> 5, k = it & 31;
            sW2[jj * 33 + k] = t2w[(size_t)jj * C2 + kt * 32 + k];
        }
        __syncthreads();
        #pragma unroll
        for (int k = 0; k < 32; k++) {
            float w = sW2[j * 33 + k];
            #pragma unroll
            for (int i = 0; i < 8; i++)
                acc[i] += sR[i * 256 + kt * 32 + k] * w;
        }
    }
    float bv = t2b[j];
    float v[8];
    #pragma unroll
    for (int i = 0; i < 8; i++) v[i] = fmaxf(acc[i] + bv, 0.f);

    #pragma unroll
    for (int i = 0; i < 8; i++) {
        __syncthreads();
        red[j] = v[i]; __syncthreads();
        for (int s = 64; s > 0; s >>= 1) {
            if (j < s) red[j] = fmaxf(red[j], red[j + s]);
            __syncthreads();
        }
        float m = red[0]; __syncthreads();
        float e = expf(v[i] - m);
        red[j] = e; __syncthreads();
        for (int s = 64; s > 0; s >>= 1) {
            if (j < s) red[j] += red[j + s];
            __syncthreads();
        }
        float sum = red[0];
        g_attnT16[((size_t)(b * CC + j)) * C2 + rg * 8 + i] =
            __float2half_rn(e / sum);
    }
}

// ================================================================ kernel 4
// out[c][n] = sum_d attnT[c][d] * vcon[n][d]; both planes via cp.async.
extern "C" __global__ void __launch_bounds__(256, 2)
k_out(float* __restrict__ out)
{
    extern __shared__ char smem[];
    u32 sb = smem_u32(smem);
    int tid = threadIdx.x, wid = tid >> 5, lane = tid & 31;
    int b = blockIdx.y, n0 = blockIdx.x * 128;
    const __half* At = g_attnT16 + (size_t)b * CC * C2;
    const __half* V = g_vcon + (size_t)b * NN * C2;

    float acc[4][4][4];
    #pragma unroll
    for (int i = 0; i < 4; i++)
        #pragma unroll
        for (int j = 0; j < 4; j++)
            #pragma unroll
            for (int e = 0; e < 4; e++) acc[i][j][e] = 0.f;

    auto fill = [&](int ch, int buf) {
        int d0 = ch * 64;
        u32 sbb = sb + buf * 36864;
        for (int it = tid; it < 1024; it += 256) {
            int c = it >> 3, seg = it & 7;
            CPA16(sbb + c * E_ST + seg * 16,
                  At + (size_t)c * C2 + d0 + seg * 8);
        }
        for (int it = tid; it < 1024; it += 256) {
            int n = it >> 3, seg = it & 7;
            CPA16(sbb + E_PL + n * E_ST + seg * 16,
                  V + (size_t)(n0 + n) * C2 + d0 + seg * 8);
        }
        CP_COMMIT();
    };

    fill(0, 0);
    for (int ch = 0; ch < 4; ch++) {
        int buf = ch & 1;
        if (ch + 1 < 4) { fill(ch + 1, (ch + 1) & 1); CP_WAIT1(); }
        else            { CP_WAIT0(); }
        __syncthreads();
        u32 base = buf * 36864;
        gemm1_k64(sb, base, base + E_PL, acc, wid, lane);
        __syncthreads();
    }

    int m0w = (wid >> 2) * 64, n0w = (wid & 3) * 32;
    int r = lane >> 2, cpo = (lane & 3) * 2;
    #pragma unroll
    for (int mi = 0; mi < 4; mi++) {
        int m = m0w + mi * 16 + r;
        #pragma unroll
        for (int ni = 0; ni < 4; ni++) {
            int n = n0w + ni * 8 + cpo;
            *(float2*)&out[((size_t)(b * CC + m)) * NN + n0 + n] =
                make_float2(acc[mi][ni][0], acc[mi][ni][1]);
            *(float2*)&out[((size_t)(b * CC + m + 8)) * NN + n0 + n] =
                make_float2(acc[mi][ni][2], acc[mi][ni][3]);
        }
    }
}

// ---------------------------------------------------------------- launch
extern "C" void kernel_launch(void* const* d_in, const int* in_sizes, int n_in,
                              void* d_out, int out_size)
{
    const float* x   = (const float*)d_in[0];
    const float* y   = (const float*)d_in[1];
    const float* qw  = (const float*)d_in[2];
    const float* qb  = (const float*)d_in[3];
    const float* kw  = (const float*)d_in[4];
    const float* kb  = (const float*)d_in[5];
    const float* v1w = (const float*)d_in[6];
    const float* v1b = (const float*)d_in[7];
    const float* v2w = (const float*)d_in[8];
    const float* v2b = (const float*)d_in[9];
    const float* t1w = (const float*)d_in[10];
    const float* t1b = (const float*)d_in[11];
    const float* t2w = (const float*)d_in[12];
    const float* t2b = (const float*)d_in[13];
    float* out = (float*)d_out;

    cudaFuncSetAttribute(k_pconv,       cudaFuncAttributeMaxDynamicSharedMemorySize, SM_PCONV);
    cudaFuncSetAttribute(k_energy_diag, cudaFuncAttributeMaxDynamicSharedMemorySize, 73728);
    cudaFuncSetAttribute(k_energy_off,  cudaFuncAttributeMaxDynamicSharedMemorySize, 2 * O_BUF);
    cudaFuncSetAttribute(k_out,         cudaFuncAttributeMaxDynamicSharedMemorySize, 73728);

    k_pconv      <<<dim3(NN / 128, BB, 2), 256, SM_PCONV>>>(x, y, qw, qb, kw, kb,
                                                            v1w, v1b, v2w, v2b);
    k_energy_diag<<<dim3(2 * ESPD, BB), 256, 73728>>>();
    k_energy_off <<<dim3(ESPO, BB), 256, 2 * O_BUF>>>();
    k_ereduce    <<<dim3(C2, BB), C2>>>();
    k_mlp1       <<<dim3(32, BB), 256>>>(t1w, t1b);
    k_mlp2       <<<dim3(32, BB), 128>>>(t2w, t2b);
    k_out        <<<dim3(NN / 128, BB), 256, 73728>>>(out);
}

// round 16
// speedup vs baseline: 4.3197x; 1.2305x over previous
#include <cuda_runtime.h>
#include <cuda_bf16.h>
#include <cuda_fp16.h>
#include <stdint.h>
#include <math.h>

#define BB 8
#define CC 128
#define C2 256
#define NN 32768
#define ESP 32            // epart slot stride
#define ESPD 16           // diag splits
#define ESPO 32           // off-diag splits

typedef unsigned int u32;
typedef unsigned long long u64;

// K=64 chunk plane geometry: [128 rows][72 halves], stride 144B
#define E_ST 144
#define E_PL 18432
// K=32 chunk plane geometry (off-diag): [256 rows][40 halves], stride 80B
#define O_ST 80
#define O_PL 20480
#define O_BUF 40960
// vcon transpose staging stride
#define ST_B 272

__device__ __forceinline__ u32 smem_u32(const void* p) {
    u32 a;
    asm("{ .reg .u64 t; cvta.to.shared.u64 t, %1; cvt.u32.u64 %0, t; }"
        : "=r"(a) : "l"(p));
    return a;
}

#define LDSM4(r, addr) \
    asm volatile("ldmatrix.sync.aligned.m8n8.x4.shared.b16 {%0,%1,%2,%3}, [%4];" \
        : "=r"((r)[0]), "=r"((r)[1]), "=r"((r)[2]), "=r"((r)[3]) : "r"(addr))

#define MMA_BF(acc, a, b0, b1) \
    asm volatile("mma.sync.aligned.m16n8k16.row.col.f32.bf16.bf16.f32 " \
        "{%0,%1,%2,%3}, {%4,%5,%6,%7}, {%8,%9}, {%0,%1,%2,%3};" \
        : "+f"((acc)[0]), "+f"((acc)[1]), "+f"((acc)[2]), "+f"((acc)[3]) \
        : "r"((a)[0]), "r"((a)[1]), "r"((a)[2]), "r"((a)[3]), "r"(b0), "r"(b1))

#define MMA_FP(acc, a, b0, b1) \
    asm volatile("mma.sync.aligned.m16n8k16.row.col.f32.f16.f16.f32 " \
        "{%0,%1,%2,%3}, {%4,%5,%6,%7}, {%8,%9}, {%0,%1,%2,%3};" \
        : "+f"((acc)[0]), "+f"((acc)[1]), "+f"((acc)[2]), "+f"((acc)[3]) \
        : "r"((a)[0]), "r"((a)[1]), "r"((a)[2]), "r"((a)[3]), "r"(b0), "r"(b1))

#define CPA16(s, g) \
    asm volatile("cp.async.cg.shared.global [%0], [%1], 16;" \
        :: "r"(s), "l"(g) : "memory")
#define CP_COMMIT() asm volatile("cp.async.commit_group;" ::: "memory")
#define CP_WAIT2()  asm volatile("cp.async.wait_group 2;" ::: "memory")
#define CP_WAIT1()  asm volatile("cp.async.wait_group 1;" ::: "memory")
#define CP_WAIT0()  asm volatile("cp.async.wait_group 0;" ::: "memory")

__device__ __forceinline__ u32 packh2(float a, float b) {
    __half2 h = __floats2half2_rn(a, b);
    return *(u32*)&h;
}
__device__ __forceinline__ u32 hilo2(float v0, float v1, u32& lopack) {
    __nv_bfloat16 h0 = __float2bfloat16_rn(v0);
    __nv_bfloat16 h1 = __float2bfloat16_rn(v1);
    __nv_bfloat16 l0 = __float2bfloat16_rn(v0 - __bfloat162float(h0));
    __nv_bfloat16 l1 = __float2bfloat16_rn(v1 - __bfloat162float(h1));
    lopack = (u32)__bfloat16_as_ushort(l0) | ((u32)__bfloat16_as_ushort(l1) << 16);
    return (u32)__bfloat16_as_ushort(h0) | ((u32)__bfloat16_as_ushort(h1) << 16);
}

// ---------------------------------------------------------------- scratch
__device__ __align__(16) __nv_bfloat16 g_xcon_hi[(size_t)BB * C2 * NN]; // [b][d][n]
__device__ __align__(16) __nv_bfloat16 g_xcon_lo[(size_t)BB * C2 * NN];
__device__ __align__(16) __half g_vcon[(size_t)BB * NN * C2];           // [b][n][d]
__device__ float g_epart[(size_t)BB * ESP * C2 * C2];                   // [b][s][i][j]
__device__ float g_energy[BB * C2 * C2];
__device__ float g_e1[BB * C2 * C2];
__device__ __align__(16) __half g_attnT16[BB * CC * C2];                // [b][c][d]

// ---------------------------------------------------------------- GEMM cores
// K=64 chunk, stride 144B
__device__ __forceinline__ void gemm3_k64(u32 sb, u32 ah_off, u32 al_off,
                                          u32 bh_off, u32 bl_off,
                                          float (&acc)[4][4][4],
                                          int wid, int lane)
{
    const int m0 = (wid >> 2) * 64, n0 = (wid & 3) * 32;
    const int row = lane & 15;
    const int half = (lane >> 4) * 16;
    #pragma unroll
    for (int ks = 0; ks < 4; ks++) {
        int kb = ks * 32 + half;
        u32 ah[4][4], al[4][4], bh[2][4], bl[2][4];
        #pragma unroll
        for (int mi = 0; mi < 4; mi++) {
            int ro = (m0 + mi * 16 + row) * E_ST + kb;
            LDSM4(ah[mi], sb + ah_off + ro);
            LDSM4(al[mi], sb + al_off + ro);
        }
        #pragma unroll
        for (int nb = 0; nb < 2; nb++) {
            int ro = (n0 + nb * 16 + row) * E_ST + kb;
            LDSM4(bh[nb], sb + bh_off + ro);
            LDSM4(bl[nb], sb + bl_off + ro);
        }
        #pragma unroll
        for (int mi = 0; mi < 4; mi++)
            #pragma unroll
            for (int ni = 0; ni < 4; ni++) {
                int nb = ni >> 1, sel = ni & 1;
                MMA_BF(acc[mi][ni], ah[mi], bh[nb][sel], bh[nb][sel + 2]);
                MMA_BF(acc[mi][ni], al[mi], bh[nb][sel], bh[nb][sel + 2]);
                MMA_BF(acc[mi][ni], ah[mi], bl[nb][sel], bl[nb][sel + 2]);
            }
    }
}

__device__ __forceinline__ void gemm1_k64(u32 sb, u32 a_off, u32 b_off,
                                          float (&acc)[4][4][4],
                                          int wid, int lane)
{
    const int m0 = (wid >> 2) * 64, n0 = (wid & 3) * 32;
    const int row = lane & 15;
    const int half = (lane >> 4) * 16;
    #pragma unroll
    for (int ks = 0; ks < 4; ks++) {
        int kb = ks * 32 + half;
        u32 ah[4][4], bh[2][4];
        #pragma unroll
        for (int mi = 0; mi < 4; mi++)
            LDSM4(ah[mi], sb + a_off + (m0 + mi * 16 + row) * E_ST + kb);
        #pragma unroll
        for (int nb = 0; nb < 2; nb++)
            LDSM4(bh[nb], sb + b_off + (n0 + nb * 16 + row) * E_ST + kb);
        #pragma unroll
        for (int mi = 0; mi < 4; mi++)
            #pragma unroll
            for (int ni = 0; ni < 4; ni++) {
                int nb = ni >> 1, sel = ni & 1;
                MMA_FP(acc[mi][ni], ah[mi], bh[nb][sel], bh[nb][sel + 2]);
            }
    }
}

// K=32 chunk, stride 80B (off-diag)
__device__ __forceinline__ void gemm3_k32(u32 sb, u32 ah_off, u32 al_off,
                                          u32 bh_off, u32 bl_off,
                                          float (&acc)[4][4][4],
                                          int wid, int lane)
{
    const int m0 = (wid >> 2) * 64, n0 = (wid & 3) * 32;
    const int row = lane & 15;
    const int half = (lane >> 4) * 16;
    #pragma unroll
    for (int ks = 0; ks < 2; ks++) {
        int kb = ks * 32 + half;
        u32 ah[4][4], al[4][4], bh[2][4], bl[2][4];
        #pragma unroll
        for (int mi = 0; mi < 4; mi++) {
            int ro = (m0 + mi * 16 + row) * O_ST + kb;
            LDSM4(ah[mi], sb + ah_off + ro);
            LDSM4(al[mi], sb + al_off + ro);
        }
        #pragma unroll
        for (int nb = 0; nb < 2; nb++) {
            int ro = (n0 + nb * 16 + row) * O_ST + kb;
            LDSM4(bh[nb], sb + bh_off + ro);
            LDSM4(bl[nb], sb + bl_off + ro);
        }
        #pragma unroll
        for (int mi = 0; mi < 4; mi++)
            #pragma unroll
            for (int ni = 0; ni < 4; ni++) {
                int nb = ni >> 1, sel = ni & 1;
                MMA_BF(acc[mi][ni], ah[mi], bh[nb][sel], bh[nb][sel + 2]);
                MMA_BF(acc[mi][ni], al[mi], bh[nb][sel], bh[nb][sel + 2]);
                MMA_BF(acc[mi][ni], ah[mi], bl[nb][sel], bl[nb][sel + 2]);
            }
    }
}

// ================================================================ kernel 1a
// q/k convs (bf16 3-product), K=64 chunks, occ 2.
// grid (256 ntiles, 8, 2 src). src0 (In=x): k_w -> xcon[128..];
// src1 (In=y): q_w -> xcon[0..].
extern "C" __global__ void __launch_bounds__(256, 2)
k_pconv_qk(const float* __restrict__ x, const float* __restrict__ y,
           const float* __restrict__ qw, const float* __restrict__ qb,
           const float* __restrict__ kw, const float* __restrict__ kb)
{
    extern __shared__ char smem[];
    u32 sb = smem_u32(smem);
    int tid = threadIdx.x, wid = tid >> 5, lane = tid & 31;
    int b = blockIdx.y, n0 = blockIdx.x * 128, src = blockIdx.z;
    const float* In = (src ? y : x) + (size_t)b * CC * NN;
    const float* W = src ? qw : kw;
    const float* bsrc = src ? qb : kb;
    int zoff = src ? 0 : 128;
    float* bias_s = (float*)(smem + 4 * E_PL);

    if (tid < 128) bias_s[tid] = bsrc[tid];

    float acc[4][4][4];
    #pragma unroll
    for (int i = 0; i < 4; i++)
        #pragma unroll
        for (int j = 0; j < 4; j++)
            #pragma unroll
            for (int e = 0; e < 4; e++) acc[i][j][e] = 0.f;

    for (int ch = 0; ch < 2; ch++) {
        int c0 = ch * 64;
        __syncthreads();
        // A = W[o][c-chunk] hi/lo
        for (int it = tid; it < 2048; it += 256) {
            int o = it >> 4, c4 = (it & 15) * 4;
            float4 v = *(const float4*)(W + o * 128 + c0 + c4);
            u32 l01, h01 = hilo2(v.x, v.y, l01);
            u32 l23, h23 = hilo2(v.z, v.w, l23);
            *(u32*)(smem + o * E_ST + c4 * 2)            = h01;
            *(u32*)(smem + o * E_ST + c4 * 2 + 4)        = h23;
            *(u32*)(smem + E_PL + o * E_ST + c4 * 2)     = l01;
            *(u32*)(smem + E_PL + o * E_ST + c4 * 2 + 4) = l23;
        }
        // B = In^T [n][c-chunk] hi/lo (coalesced along n)
        for (int it = tid; it < 2048; it += 256) {
            int c = it >> 5, j = it & 31;
            #pragma unroll
            for (int q = 0; q < 4; q++) {
                int n = j + q * 32;
                float v = In[(size_t)(c0 + c) * NN + n0 + n];
                __nv_bfloat16 h = __float2bfloat16_rn(v);
                __nv_bfloat16 l = __float2bfloat16_rn(v - __bfloat162float(h));
                *(__nv_bfloat16*)(smem + 2 * E_PL + n * E_ST + c * 2) = h;
                *(__nv_bfloat16*)(smem + 3 * E_PL + n * E_ST + c * 2) = l;
            }
        }
        __syncthreads();
        gemm3_k64(sb, 0, E_PL, 2 * E_PL, 3 * E_PL, acc, wid, lane);
    }

    int m0w = (wid >> 2) * 64, n0w = (wid & 3) * 32;
    int r = lane >> 2, cpo = (lane & 3) * 2;
    #pragma unroll
    for (int mi = 0; mi < 4; mi++) {
        int o = m0w + mi * 16 + r;
        float bb0 = bias_s[o], bb8 = bias_s[o + 8];
        #pragma unroll
        for (int ni = 0; ni < 4; ni++) {
            int n = n0w + ni * 8 + cpo;
            u32 lp, hp;
            hp = hilo2(acc[mi][ni][0] + bb0, acc[mi][ni][1] + bb0, lp);
            size_t gi = ((size_t)(b * C2 + zoff + o)) * NN + n0 + n;
            *(u32*)&g_xcon_hi[gi] = hp;
            *(u32*)&g_xcon_lo[gi] = lp;
            hp = hilo2(acc[mi][ni][2] + bb8, acc[mi][ni][3] + bb8, lp);
            gi = ((size_t)(b * C2 + zoff + o + 8)) * NN + n0 + n;
            *(u32*)&g_xcon_hi[gi] = hp;
            *(u32*)&g_xcon_lo[gi] = lp;
        }
    }
}

// ================================================================ kernel 1b
// v convs (fp16 1-product), K=64 chunks, 2 planes, occ 2.
// src0 (In=x): v1_w -> vcon[..][128..]; src1 (In=y): v2_w -> vcon[..][0..].
extern "C" __global__ void __launch_bounds__(256, 2)
k_pconv_v(const float* __restrict__ x, const float* __restrict__ y,
          const float* __restrict__ v1w, const float* __restrict__ v1b,
          const float* __restrict__ v2w, const float* __restrict__ v2b)
{
    extern __shared__ char smem[];
    u32 sb = smem_u32(smem);
    int tid = threadIdx.x, wid = tid >> 5, lane = tid & 31;
    int b = blockIdx.y, n0 = blockIdx.x * 128, src = blockIdx.z;
    const float* In = (src ? y : x) + (size_t)b * CC * NN;
    const float* W = src ? v2w : v1w;
    const float* bsrc = src ? v2b : v1b;
    int zoff = src ? 0 : 128;
    float* bias_s = (float*)(smem + 2 * E_PL);

    if (tid < 128) bias_s[tid] = bsrc[tid];

    float acc[4][4][4];
    #pragma unroll
    for (int i = 0; i < 4; i++)
        #pragma unroll
        for (int j = 0; j < 4; j++)
            #pragma unroll
            for (int e = 0; e < 4; e++) acc[i][j][e] = 0.f;

    for (int ch = 0; ch < 2; ch++) {
        int c0 = ch * 64;
        __syncthreads();
        for (int it = tid; it < 2048; it += 256) {
            int o = it >> 4, c4 = (it & 15) * 4;
            float4 v = *(const float4*)(W + o * 128 + c0 + c4);
            *(u32*)(smem + o * E_ST + c4 * 2)     = packh2(v.x, v.y);
            *(u32*)(smem + o * E_ST + c4 * 2 + 4) = packh2(v.z, v.w);
        }
        for (int it = tid; it < 2048; it += 256) {
            int c = it >> 5, j = it & 31;
            #pragma unroll
            for (int q = 0; q < 4; q++) {
                int n = j + q * 32;
                float v = In[(size_t)(c0 + c) * NN + n0 + n];
                *(__half*)(smem + E_PL + n * E_ST + c * 2) = __float2half_rn(v);
            }
        }
        __syncthreads();
        gemm1_k64(sb, 0, E_PL, acc, wid, lane);
    }

    // transpose to vcon[n0+n][zoff+o] via staging (reuse plane region)
    __syncthreads();
    int m0w = (wid >> 2) * 64, n0w = (wid & 3) * 32;
    int r = lane >> 2, cpo = (lane & 3) * 2;
    #pragma unroll
    for (int mi = 0; mi < 4; mi++) {
        int o = m0w + mi * 16 + r;
        float bb0 = bias_s[o], bb8 = bias_s[o + 8];
        #pragma unroll
        for (int ni = 0; ni < 4; ni++) {
            int n = n0w + ni * 8 + cpo;
            #pragma unroll
            for (int e = 0; e < 4; e++) {
                float v = acc[mi][ni][e] + ((e >= 2) ? bb8 : bb0);
                int oo = o + ((e >= 2) ? 8 : 0);
                int nn = n + (e & 1);
                *(__half*)(smem + nn * ST_B + oo * 2) = __float2half_rn(v);
            }
        }
    }
    __syncthreads();
    for (int it = tid; it < 128 * 64; it += 256) {
        int n = it >> 6, w = it & 63;
        u32 val = *(u32*)(smem + n * ST_B + w * 4);
        *((u32*)(g_vcon + ((size_t)(b * NN + n0 + n)) * C2 + zoff) + w) = val;
    }
}

// ================================================================ kernel 2a
// energy DIAG Gram tiles: ESPD=16 splits, 32 chunks K=64, 3-stage pipeline.
extern "C" __global__ void __launch_bounds__(256, 2)
k_energy_diag()
{
    extern __shared__ char smem[];
    u32 sb = smem_u32(smem);
    int tid = threadIdx.x, wid = tid >> 5, lane = tid & 31;
    int b = blockIdx.y;
    int t = blockIdx.x >> 4, sp = blockIdx.x & 15;
    int i0 = t * 128;
    const __nv_bfloat16* Xh = g_xcon_hi + (size_t)b * C2 * NN;
    const __nv_bfloat16* Xl = g_xcon_lo + (size_t)b * C2 * NN;
    int k0 = sp * 2048;

    float acc[4][4][4];
    #pragma unroll
    for (int i = 0; i < 4; i++)
        #pragma unroll
        for (int j = 0; j < 4; j++)
            #pragma unroll
            for (int e = 0; e < 4; e++) acc[i][j][e] = 0.f;

    auto issue = [&](int ch, int buf) {
        int kb = k0 + ch * 64;
        for (int it = tid; it < 2048; it += 256) {
            int pl = it >> 10, r = (it >> 3) & 127, seg = it & 7;
            const __nv_bfloat16* src =
                (pl ? Xl : Xh) + (size_t)(i0 + r) * NN + kb + seg * 8;
            CPA16(sb + buf * 36864 + pl * E_PL + r * E_ST + seg * 16, src);
        }
        CP_COMMIT();
    };

    issue(0, 0);
    issue(1, 1);
    for (int ch = 0; ch < 32; ch++) {
        int buf = ch % 3;
        if (ch + 2 < 32) { issue(ch + 2, (ch + 2) % 3); CP_WAIT2(); }
        else if (ch + 1 < 32) { CP_WAIT1(); }
        else { CP_WAIT0(); }
        __syncthreads();
        u32 base = buf * 36864;
        gemm3_k64(sb, base, base + E_PL, base, base + E_PL, acc, wid, lane);
        __syncthreads();
    }

    int m0w = (wid >> 2) * 64, n0w = (wid & 3) * 32;
    int r = lane >> 2, cpo = (lane & 3) * 2;
    float* Ep = g_epart + ((size_t)(b * ESP + sp)) * C2 * C2;
    #pragma unroll
    for (int mi = 0; mi < 4; mi++) {
        int i = i0 + m0w + mi * 16 + r;
        #pragma unroll
        for (int ni = 0; ni < 4; ni++) {
            int j = i0 + n0w + ni * 8 + cpo;
            *(float2*)&Ep[(size_t)i * C2 + j] =
                make_float2(acc[mi][ni][0], acc[mi][ni][1]);
            *(float2*)&Ep[(size_t)(i + 8) * C2 + j] =
                make_float2(acc[mi][ni][2], acc[mi][ni][3]);
        }
    }
}

// ================================================================ kernel 2b
// energy OFF-DIAG: ESPO=32 splits, K=32 chunks, 256-row plane pair, occ 2.
extern "C" __global__ void __launch_bounds__(256, 2)
k_energy_off()
{
    extern __shared__ char smem[];
    u32 sb = smem_u32(smem);
    int tid = threadIdx.x, wid = tid >> 5, lane = tid & 31;
    int b = blockIdx.y, sp = blockIdx.x;
    const __nv_bfloat16* Xh = g_xcon_hi + (size_t)b * C2 * NN;
    const __nv_bfloat16* Xl = g_xcon_lo + (size_t)b * C2 * NN;
    int k0 = sp * 1024;

    float acc[4][4][4];
    #pragma unroll
    for (int i = 0; i < 4; i++)
        #pragma unroll
        for (int j = 0; j < 4; j++)
            #pragma unroll
            for (int e = 0; e < 4; e++) acc[i][j][e] = 0.f;

    auto issue = [&](int ch, int buf) {
        int kb = k0 + ch * 32;
        for (int it = tid; it < 2048; it += 256) {
            int pl = it >> 10, r = (it >> 2) & 255, seg = it & 3;
            const __nv_bfloat16* src =
                (pl ? Xl : Xh) + (size_t)r * NN + kb + seg * 8;
            CPA16(sb + buf * O_BUF + pl * O_PL + r * O_ST + seg * 16, src);
        }
        CP_COMMIT();
    };

    issue(0, 0);
    for (int ch = 0; ch < 32; ch++) {
        int buf = ch & 1;
        if (ch + 1 < 32) { issue(ch + 1, (ch + 1) & 1); CP_WAIT1(); }
        else             { CP_WAIT0(); }
        __syncthreads();
        u32 base = buf * O_BUF;
        gemm3_k32(sb, base, base + O_PL,
                  base + 128 * O_ST, base + O_PL + 128 * O_ST, acc, wid, lane);
        __syncthreads();
    }

    int m0w = (wid >> 2) * 64, n0w = (wid & 3) * 32;
    int r = lane >> 2, cpo = (lane & 3) * 2;
    float* Ep = g_epart + ((size_t)(b * ESP + sp)) * C2 * C2;
    #pragma unroll
    for (int mi = 0; mi < 4; mi++) {
        int i = m0w + mi * 16 + r;
        #pragma unroll
        for (int ni = 0; ni < 4; ni++) {
            int j = 128 + n0w + ni * 8 + cpo;
            *(float2*)&Ep[(size_t)i * C2 + j] =
                make_float2(acc[mi][ni][0], acc[mi][ni][1]);
            *(float2*)&Ep[(size_t)(i + 8) * C2 + j] =
                make_float2(acc[mi][ni][2], acc[mi][ni][3]);
        }
    }
}

// ================================================================ kernel 2c
// unrolled fixed-count split loops (MLP covers L2 latency)
extern "C" __global__ void k_ereduce()
{
    int j = threadIdx.x, i = blockIdx.x, b = blockIdx.y;
    bool offq = (i < 128) != (j < 128);
    int si = i, sj = j;
    if (i >= 128 && j < 128) { si = j; sj = i; }
    size_t base = ((size_t)(b * ESP) * C2 + si) * C2 + sj;
    const size_t str = (size_t)C2 * C2;
    float s0 = 0.f, s1 = 0.f, s2 = 0.f, s3 = 0.f;
    if (offq) {
        #pragma unroll
        for (int sp = 0; sp < 32; sp += 4) {
            s0 += g_epart[base + (size_t)(sp + 0) * str];
            s1 += g_epart[base + (size_t)(sp + 1) * str];
            s2 += g_epart[base + (size_t)(sp + 2) * str];
            s3 += g_epart[base + (size_t)(sp + 3) * str];
        }
    } else {
        #pragma unroll
        for (int sp = 0; sp < 16; sp += 4) {
            s0 += g_epart[base + (size_t)(sp + 0) * str];
            s1 += g_epart[base + (size_t)(sp + 1) * str];
            s2 += g_epart[base + (size_t)(sp + 2) * str];
            s3 += g_epart[base + (size_t)(sp + 3) * str];
        }
    }
    g_energy[((size_t)b * C2 + i) * C2 + j] =
        ((s0 + s1) + (s2 + s3)) * (1.0f / 16.0f);
}

// ================================================================ kernel 3a
extern "C" __global__ void __launch_bounds__(256)
k_mlp1(const float* __restrict__ t1w, const float* __restrict__ t1b)
{
    __shared__ float sE[8 * 256];
    __shared__ float sW[256 * 33];
    int b = blockIdx.y, rg = blockIdx.x;
    int tid = threadIdx.x;
    const float* E = g_energy + (size_t)b * C2 * C2 + (size_t)rg * 8 * C2;
    #pragma unroll
    for (int t = 0; t < 8; t++) sE[t * 256 + tid] = E[t * 256 + tid];

    float acc[8];
    #pragma unroll
    for (int i = 0; i < 8; i++) acc[i] = 0.f;

    for (int kt = 0; kt < 8; kt++) {
        __syncthreads();
        for (int it = tid; it < 8192; it += 256) {
            int j = it >> 5, k = it & 31;
            sW[j * 33 + k] = t1w[(size_t)j * C2 + kt * 32 + k];
        }
        __syncthreads();
        #pragma unroll
        for (int k = 0; k < 32; k++) {
            float w = sW[tid * 33 + k];
            #pragma unroll
            for (int i = 0; i < 8; i++)
                acc[i] += sE[i * 256 + kt * 32 + k] * w;
        }
    }
    float bv = t1b[tid];
    float* O = g_e1 + (size_t)b * C2 * C2 + (size_t)rg * 8 * C2;
    #pragma unroll
    for (int i = 0; i < 8; i++)
        O[i * 256 + tid] = fmaxf(acc[i] + bv, 0.f);
}

// ================================================================ kernel 3b
extern "C" __global__ void __launch_bounds__(128)
k_mlp2(const float* __restrict__ t2w, const float* __restrict__ t2b)
{
    __shared__ float sR[8 * 256];
    __shared__ float sW2[128 * 33];
    __shared__ float red[128];
    int b = blockIdx.y, rg = blockIdx.x, j = threadIdx.x;
    const float* E1 = g_e1 + (size_t)b * C2 * C2 + (size_t)rg * 8 * C2;
    for (int it = j; it < 2048; it += 128) sR[it] = E1[it];

    float acc[8];
    #pragma unroll
    for (int i = 0; i < 8; i++) acc[i] = 0.f;

    for (int kt = 0; kt < 8; kt++) {
        __syncthreads();
        for (int it = j; it < 4096; it += 128) {
            int jj = it >> 5, k = it & 31;
            sW2[jj * 33 + k] = t2w[(size_t)jj * C2 + kt * 32 + k];
        }
        __syncthreads();
        #pragma unroll
        for (int k = 0; k < 32; k++) {
            float w = sW2[j * 33 + k];
            #pragma unroll
            for (int i = 0; i < 8; i++)
                acc[i] += sR[i * 256 + kt * 32 + k] * w;
        }
    }
    float bv = t2b[j];
    float v[8];
    #pragma unroll
    for (int i = 0; i < 8; i++) v[i] = fmaxf(acc[i] + bv, 0.f);

    #pragma unroll
    for (int i = 0; i < 8; i++) {
        __syncthreads();
        red[j] = v[i]; __syncthreads();
        for (int s = 64; s > 0; s >>= 1) {
            if (j < s) red[j] = fmaxf(red[j], red[j + s]);
            __syncthreads();
        }
        float m = red[0]; __syncthreads();
        float e = expf(v[i] - m);
        red[j] = e; __syncthreads();
        for (int s = 64; s > 0; s >>= 1) {
            if (j < s) red[j] += red[j + s];
            __syncthreads();
        }
        float sum = red[0];
        g_attnT16[((size_t)(b * CC + j)) * C2 + rg * 8 + i] =
            __float2half_rn(e / sum);
    }
}

// ================================================================ kernel 4
extern "C" __global__ void __launch_bounds__(256, 2)
k_out(float* __restrict__ out)
{
    extern __shared__ char smem[];
    u32 sb = smem_u32(smem);
    int tid = threadIdx.x, wid = tid >> 5, lane = tid & 31;
    int b = blockIdx.y, n0 = blockIdx.x * 128;
    const __half* At = g_attnT16 + (size_t)b * CC * C2;
    const __half* V = g_vcon + (size_t)b * NN * C2;

    float acc[4][4][4];
    #pragma unroll
    for (int i = 0; i < 4; i++)
        #pragma unroll
        for (int j = 0; j < 4; j++)
            #pragma unroll
            for (int e = 0; e < 4; e++) acc[i][j][e] = 0.f;

    auto fill = [&](int ch, int buf) {
        int d0 = ch * 64;
        u32 sbb = sb + buf * 36864;
        for (int it = tid; it < 1024; it += 256) {
            int c = it >> 3, seg = it & 7;
            CPA16(sbb + c * E_ST + seg * 16,
                  At + (size_t)c * C2 + d0 + seg * 8);
        }
        for (int it = tid; it < 1024; it += 256) {
            int n = it >> 3, seg = it & 7;
            CPA16(sbb + E_PL + n * E_ST + seg * 16,
                  V + (size_t)(n0 + n) * C2 + d0 + seg * 8);
        }
        CP_COMMIT();
    };

    fill(0, 0);
    for (int ch = 0; ch < 4; ch++) {
        int buf = ch & 1;
        if (ch + 1 < 4) { fill(ch + 1, (ch + 1) & 1); CP_WAIT1(); }
        else            { CP_WAIT0(); }
        __syncthreads();
        u32 base = buf * 36864;
        gemm1_k64(sb, base, base + E_PL, acc, wid, lane);
        __syncthreads();
    }

    int m0w = (wid >> 2) * 64, n0w = (wid & 3) * 32;
    int r = lane >> 2, cpo = (lane & 3) * 2;
    #pragma unroll
    for (int mi = 0; mi < 4; mi++) {
        int m = m0w + mi * 16 + r;
        #pragma unroll
        for (int ni = 0; ni < 4; ni++) {
            int n = n0w + ni * 8 + cpo;
            *(float2*)&out[((size_t)(b * CC + m)) * NN + n0 + n] =
                make_float2(acc[mi][ni][0], acc[mi][ni][1]);
            *(float2*)&out[((size_t)(b * CC + m + 8)) * NN + n0 + n] =
                make_float2(acc[mi][ni][2], acc[mi][ni][3]);
        }
    }
}

// ---------------------------------------------------------------- launch
extern "C" void kernel_launch(void* const* d_in, const int* in_sizes, int n_in,
                              void* d_out, int out_size)
{
    const float* x   = (const float*)d_in[0];
    const float* y   = (const float*)d_in[1];
    const float* qw  = (const float*)d_in[2];
    const float* qb  = (const float*)d_in[3];
    const float* kw  = (const float*)d_in[4];
    const float* kb  = (const float*)d_in[5];
    const float* v1w = (const float*)d_in[6];
    const float* v1b = (const float*)d_in[7];
    const float* v2w = (const float*)d_in[8];
    const float* v2b = (const float*)d_in[9];
    const float* t1w = (const float*)d_in[10];
    const float* t1b = (const float*)d_in[11];
    const float* t2w = (const float*)d_in[12];
    const float* t2b = (const float*)d_in[13];
    float* out = (float*)d_out;

    cudaFuncSetAttribute(k_pconv_qk,    cudaFuncAttributeMaxDynamicSharedMemorySize, 4 * E_PL + 512);
    cudaFuncSetAttribute(k_pconv_v,     cudaFuncAttributeMaxDynamicSharedMemorySize, 2 * E_PL + 512);
    cudaFuncSetAttribute(k_energy_diag, cudaFuncAttributeMaxDynamicSharedMemorySize, 110592);
    cudaFuncSetAttribute(k_energy_off,  cudaFuncAttributeMaxDynamicSharedMemorySize, 2 * O_BUF);
    cudaFuncSetAttribute(k_out,         cudaFuncAttributeMaxDynamicSharedMemorySize, 73728);

    k_pconv_qk   <<<dim3(NN / 128, BB, 2), 256, 4 * E_PL + 512>>>(x, y, qw, qb, kw, kb);
    k_pconv_v    <<<dim3(NN / 128, BB, 2), 256, 2 * E_PL + 512>>>(x, y, v1w, v1b, v2w, v2b);
    k_energy_diag<<<dim3(2 * ESPD, BB), 256, 110592>>>();
    k_energy_off <<<dim3(ESPO, BB), 256, 2 * O_BUF>>>();
    k_ereduce    <<<dim3(C2, BB), C2>>>();
    k_mlp1       <<<dim3(32, BB), 256>>>(t1w, t1b);
    k_mlp2       <<<dim3(32, BB), 128>>>(t2w, t2b);
    k_out        <<<dim3(NN / 128, BB), 256, 73728>>>(out);
}

// round 17
// speedup vs baseline: 4.3662x; 1.0108x over previous
#include <cuda_runtime.h>
#include <cuda_bf16.h>
#include <cuda_fp16.h>
#include <stdint.h>
#include <math.h>

#define BB 8
#define CC 128
#define C2 256
#define NN 32768
#define ESP 16            // unified splits (all tiles)

typedef unsigned int u32;
typedef unsigned long long u64;

// K=64 chunk plane geometry: [128 rows][72 halves], stride 144B
#define E_ST 144
#define E_PL 18432
// K=32 chunk plane geometry (off-diag): [256 rows][40 halves], stride 80B
#define O_ST 80
#define O_PL 20480
#define O_BUF 40960
// vcon transpose staging stride
#define ST_B 272

__device__ __forceinline__ u32 smem_u32(const void* p) {
    u32 a;
    asm("{ .reg .u64 t; cvta.to.shared.u64 t, %1; cvt.u32.u64 %0, t; }"
        : "=r"(a) : "l"(p));
    return a;
}

#define LDSM4(r, addr) \
    asm volatile("ldmatrix.sync.aligned.m8n8.x4.shared.b16 {%0,%1,%2,%3}, [%4];" \
        : "=r"((r)[0]), "=r"((r)[1]), "=r"((r)[2]), "=r"((r)[3]) : "r"(addr))

#define MMA_BF(acc, a, b0, b1) \
    asm volatile("mma.sync.aligned.m16n8k16.row.col.f32.bf16.bf16.f32 " \
        "{%0,%1,%2,%3}, {%4,%5,%6,%7}, {%8,%9}, {%0,%1,%2,%3};" \
        : "+f"((acc)[0]), "+f"((acc)[1]), "+f"((acc)[2]), "+f"((acc)[3]) \
        : "r"((a)[0]), "r"((a)[1]), "r"((a)[2]), "r"((a)[3]), "r"(b0), "r"(b1))

#define MMA_FP(acc, a, b0, b1) \
    asm volatile("mma.sync.aligned.m16n8k16.row.col.f32.f16.f16.f32 " \
        "{%0,%1,%2,%3}, {%4,%5,%6,%7}, {%8,%9}, {%0,%1,%2,%3};" \
        : "+f"((acc)[0]), "+f"((acc)[1]), "+f"((acc)[2]), "+f"((acc)[3]) \
        : "r"((a)[0]), "r"((a)[1]), "r"((a)[2]), "r"((a)[3]), "r"(b0), "r"(b1))

#define CPA16(s, g) \
    asm volatile("cp.async.cg.shared.global [%0], [%1], 16;" \
        :: "r"(s), "l"(g) : "memory")
#define CP_COMMIT() asm volatile("cp.async.commit_group;" ::: "memory")
#define CP_WAIT2()  asm volatile("cp.async.wait_group 2;" ::: "memory")
#define CP_WAIT1()  asm volatile("cp.async.wait_group 1;" ::: "memory")
#define CP_WAIT0()  asm volatile("cp.async.wait_group 0;" ::: "memory")

__device__ __forceinline__ u32 packh2(float a, float b) {
    __half2 h = __floats2half2_rn(a, b);
    return *(u32*)&h;
}
__device__ __forceinline__ u32 hilo2(float v0, float v1, u32& lopack) {
    __nv_bfloat16 h0 = __float2bfloat16_rn(v0);
    __nv_bfloat16 h1 = __float2bfloat16_rn(v1);
    __nv_bfloat16 l0 = __float2bfloat16_rn(v0 - __bfloat162float(h0));
    __nv_bfloat16 l1 = __float2bfloat16_rn(v1 - __bfloat162float(h1));
    lopack = (u32)__bfloat16_as_ushort(l0) | ((u32)__bfloat16_as_ushort(l1) << 16);
    return (u32)__bfloat16_as_ushort(h0) | ((u32)__bfloat16_as_ushort(h1) << 16);
}

// ---------------------------------------------------------------- scratch
__device__ __align__(16) __nv_bfloat16 g_xcon_hi[(size_t)BB * C2 * NN]; // [b][d][n]
__device__ __align__(16) __nv_bfloat16 g_xcon_lo[(size_t)BB * C2 * NN];
__device__ __align__(16) __half g_vcon[(size_t)BB * NN * C2];           // [b][n][d]
__device__ float g_epart[(size_t)BB * ESP * C2 * C2];                   // [b][s][i][j]
__device__ float g_energy[BB * C2 * C2];
__device__ float g_e1[BB * C2 * C2];
__device__ __align__(16) __half g_attnT16[BB * CC * C2];                // [b][c][d]

// ---------------------------------------------------------------- GEMM cores
// K=64 chunk, stride 144B
__device__ __forceinline__ void gemm3_k64(u32 sb, u32 ah_off, u32 al_off,
                                          u32 bh_off, u32 bl_off,
                                          float (&acc)[4][4][4],
                                          int wid, int lane)
{
    const int m0 = (wid >> 2) * 64, n0 = (wid & 3) * 32;
    const int row = lane & 15;
    const int half = (lane >> 4) * 16;
    #pragma unroll
    for (int ks = 0; ks < 4; ks++) {
        int kb = ks * 32 + half;
        u32 ah[4][4], al[4][4], bh[2][4], bl[2][4];
        #pragma unroll
        for (int mi = 0; mi < 4; mi++) {
            int ro = (m0 + mi * 16 + row) * E_ST + kb;
            LDSM4(ah[mi], sb + ah_off + ro);
            LDSM4(al[mi], sb + al_off + ro);
        }
        #pragma unroll
        for (int nb = 0; nb < 2; nb++) {
            int ro = (n0 + nb * 16 + row) * E_ST + kb;
            LDSM4(bh[nb], sb + bh_off + ro);
            LDSM4(bl[nb], sb + bl_off + ro);
        }
        #pragma unroll
        for (int mi = 0; mi < 4; mi++)
            #pragma unroll
            for (int ni = 0; ni < 4; ni++) {
                int nb = ni >> 1, sel = ni & 1;
                MMA_BF(acc[mi][ni], ah[mi], bh[nb][sel], bh[nb][sel + 2]);
                MMA_BF(acc[mi][ni], al[mi], bh[nb][sel], bh[nb][sel + 2]);
                MMA_BF(acc[mi][ni], ah[mi], bl[nb][sel], bl[nb][sel + 2]);
            }
    }
}

__device__ __forceinline__ void gemm1_k64(u32 sb, u32 a_off, u32 b_off,
                                          float (&acc)[4][4][4],
                                          int wid, int lane)
{
    const int m0 = (wid >> 2) * 64, n0 = (wid & 3) * 32;
    const int row = lane & 15;
    const int half = (lane >> 4) * 16;
    #pragma unroll
    for (int ks = 0; ks < 4; ks++) {
        int kb = ks * 32 + half;
        u32 ah[4][4], bh[2][4];
        #pragma unroll
        for (int mi = 0; mi < 4; mi++)
            LDSM4(ah[mi], sb + a_off + (m0 + mi * 16 + row) * E_ST + kb);
        #pragma unroll
        for (int nb = 0; nb < 2; nb++)
            LDSM4(bh[nb], sb + b_off + (n0 + nb * 16 + row) * E_ST + kb);
        #pragma unroll
        for (int mi = 0; mi < 4; mi++)
            #pragma unroll
            for (int ni = 0; ni < 4; ni++) {
                int nb = ni >> 1, sel = ni & 1;
                MMA_FP(acc[mi][ni], ah[mi], bh[nb][sel], bh[nb][sel + 2]);
            }
    }
}

// K=32 chunk, stride 80B (off-diag)
__device__ __forceinline__ void gemm3_k32(u32 sb, u32 ah_off, u32 al_off,
                                          u32 bh_off, u32 bl_off,
                                          float (&acc)[4][4][4],
                                          int wid, int lane)
{
    const int m0 = (wid >> 2) * 64, n0 = (wid & 3) * 32;
    const int row = lane & 15;
    const int half = (lane >> 4) * 16;
    #pragma unroll
    for (int ks = 0; ks < 2; ks++) {
        int kb = ks * 32 + half;
        u32 ah[4][4], al[4][4], bh[2][4], bl[2][4];
        #pragma unroll
        for (int mi = 0; mi < 4; mi++) {
            int ro = (m0 + mi * 16 + row) * O_ST + kb;
            LDSM4(ah[mi], sb + ah_off + ro);
            LDSM4(al[mi], sb + al_off + ro);
        }
        #pragma unroll
        for (int nb = 0; nb < 2; nb++) {
            int ro = (n0 + nb * 16 + row) * O_ST + kb;
            LDSM4(bh[nb], sb + bh_off + ro);
            LDSM4(bl[nb], sb + bl_off + ro);
        }
        #pragma unroll
        for (int mi = 0; mi < 4; mi++)
            #pragma unroll
            for (int ni = 0; ni < 4; ni++) {
                int nb = ni >> 1, sel = ni & 1;
                MMA_BF(acc[mi][ni], ah[mi], bh[nb][sel], bh[nb][sel + 2]);
                MMA_BF(acc[mi][ni], al[mi], bh[nb][sel], bh[nb][sel + 2]);
                MMA_BF(acc[mi][ni], ah[mi], bl[nb][sel], bl[nb][sel + 2]);
            }
    }
}

// ================================================================ kernel 1a
// q/k convs (bf16 3-product), K=64 chunks, occ 2.
extern "C" __global__ void __launch_bounds__(256, 2)
k_pconv_qk(const float* __restrict__ x, const float* __restrict__ y,
           const float* __restrict__ qw, const float* __restrict__ qb,
           const float* __restrict__ kw, const float* __restrict__ kb)
{
    extern __shared__ char smem[];
    u32 sb = smem_u32(smem);
    int tid = threadIdx.x, wid = tid >> 5, lane = tid & 31;
    int b = blockIdx.y, n0 = blockIdx.x * 128, src = blockIdx.z;
    const float* In = (src ? y : x) + (size_t)b * CC * NN;
    const float* W = src ? qw : kw;
    const float* bsrc = src ? qb : kb;
    int zoff = src ? 0 : 128;
    float* bias_s = (float*)(smem + 4 * E_PL);

    if (tid < 128) bias_s[tid] = bsrc[tid];

    float acc[4][4][4];
    #pragma unroll
    for (int i = 0; i < 4; i++)
        #pragma unroll
        for (int j = 0; j < 4; j++)
            #pragma unroll
            for (int e = 0; e < 4; e++) acc[i][j][e] = 0.f;

    for (int ch = 0; ch < 2; ch++) {
        int c0 = ch * 64;
        __syncthreads();
        for (int it = tid; it < 2048; it += 256) {
            int o = it >> 4, c4 = (it & 15) * 4;
            float4 v = *(const float4*)(W + o * 128 + c0 + c4);
            u32 l01, h01 = hilo2(v.x, v.y, l01);
            u32 l23, h23 = hilo2(v.z, v.w, l23);
            *(u32*)(smem + o * E_ST + c4 * 2)            = h01;
            *(u32*)(smem + o * E_ST + c4 * 2 + 4)        = h23;
            *(u32*)(smem + E_PL + o * E_ST + c4 * 2)     = l01;
            *(u32*)(smem + E_PL + o * E_ST + c4 * 2 + 4) = l23;
        }
        for (int it = tid; it < 2048; it += 256) {
            int c = it >> 5, j = it & 31;
            #pragma unroll
            for (int q = 0; q < 4; q++) {
                int n = j + q * 32;
                float v = In[(size_t)(c0 + c) * NN + n0 + n];
                __nv_bfloat16 h = __float2bfloat16_rn(v);
                __nv_bfloat16 l = __float2bfloat16_rn(v - __bfloat162float(h));
                *(__nv_bfloat16*)(smem + 2 * E_PL + n * E_ST + c * 2) = h;
                *(__nv_bfloat16*)(smem + 3 * E_PL + n * E_ST + c * 2) = l;
            }
        }
        __syncthreads();
        gemm3_k64(sb, 0, E_PL, 2 * E_PL, 3 * E_PL, acc, wid, lane);
    }

    int m0w = (wid >> 2) * 64, n0w = (wid & 3) * 32;
    int r = lane >> 2, cpo = (lane & 3) * 2;
    #pragma unroll
    for (int mi = 0; mi < 4; mi++) {
        int o = m0w + mi * 16 + r;
        float bb0 = bias_s[o], bb8 = bias_s[o + 8];
        #pragma unroll
        for (int ni = 0; ni < 4; ni++) {
            int n = n0w + ni * 8 + cpo;
            u32 lp, hp;
            hp = hilo2(acc[mi][ni][0] + bb0, acc[mi][ni][1] + bb0, lp);
            size_t gi = ((size_t)(b * C2 + zoff + o)) * NN + n0 + n;
            *(u32*)&g_xcon_hi[gi] = hp;
            *(u32*)&g_xcon_lo[gi] = lp;
            hp = hilo2(acc[mi][ni][2] + bb8, acc[mi][ni][3] + bb8, lp);
            gi = ((size_t)(b * C2 + zoff + o + 8)) * NN + n0 + n;
            *(u32*)&g_xcon_hi[gi] = hp;
            *(u32*)&g_xcon_lo[gi] = lp;
        }
    }
}

// ================================================================ kernel 1b
// v convs (fp16 1-product), K=64 chunks, 2 planes, occ 2.
extern "C" __global__ void __launch_bounds__(256, 2)
k_pconv_v(const float* __restrict__ x, const float* __restrict__ y,
          const float* __restrict__ v1w, const float* __restrict__ v1b,
          const float* __restrict__ v2w, const float* __restrict__ v2b)
{
    extern __shared__ char smem[];
    u32 sb = smem_u32(smem);
    int tid = threadIdx.x, wid = tid >> 5, lane = tid & 31;
    int b = blockIdx.y, n0 = blockIdx.x * 128, src = blockIdx.z;
    const float* In = (src ? y : x) + (size_t)b * CC * NN;
    const float* W = src ? v2w : v1w;
    const float* bsrc = src ? v2b : v1b;
    int zoff = src ? 0 : 128;
    float* bias_s = (float*)(smem + 2 * E_PL);

    if (tid < 128) bias_s[tid] = bsrc[tid];

    float acc[4][4][4];
    #pragma unroll
    for (int i = 0; i < 4; i++)
        #pragma unroll
        for (int j = 0; j < 4; j++)
            #pragma unroll
            for (int e = 0; e < 4; e++) acc[i][j][e] = 0.f;

    for (int ch = 0; ch < 2; ch++) {
        int c0 = ch * 64;
        __syncthreads();
        for (int it = tid; it < 2048; it += 256) {
            int o = it >> 4, c4 = (it & 15) * 4;
            float4 v = *(const float4*)(W + o * 128 + c0 + c4);
            *(u32*)(smem + o * E_ST + c4 * 2)     = packh2(v.x, v.y);
            *(u32*)(smem + o * E_ST + c4 * 2 + 4) = packh2(v.z, v.w);
        }
        for (int it = tid; it < 2048; it += 256) {
            int c = it >> 5, j = it & 31;
            #pragma unroll
            for (int q = 0; q < 4; q++) {
                int n = j + q * 32;
                float v = In[(size_t)(c0 + c) * NN + n0 + n];
                *(__half*)(smem + E_PL + n * E_ST + c * 2) = __float2half_rn(v);
            }
        }
        __syncthreads();
        gemm1_k64(sb, 0, E_PL, acc, wid, lane);
    }

    __syncthreads();
    int m0w = (wid >> 2) * 64, n0w = (wid & 3) * 32;
    int r = lane >> 2, cpo = (lane & 3) * 2;
    #pragma unroll
    for (int mi = 0; mi < 4; mi++) {
        int o = m0w + mi * 16 + r;
        float bb0 = bias_s[o], bb8 = bias_s[o + 8];
        #pragma unroll
        for (int ni = 0; ni < 4; ni++) {
            int n = n0w + ni * 8 + cpo;
            #pragma unroll
            for (int e = 0; e < 4; e++) {
                float v = acc[mi][ni][e] + ((e >= 2) ? bb8 : bb0);
                int oo = o + ((e >= 2) ? 8 : 0);
                int nn = n + (e & 1);
                *(__half*)(smem + nn * ST_B + oo * 2) = __float2half_rn(v);
            }
        }
    }
    __syncthreads();
    for (int it = tid; it < 128 * 64; it += 256) {
        int n = it >> 6, w = it & 63;
        u32 val = *(u32*)(smem + n * ST_B + w * 4);
        *((u32*)(g_vcon + ((size_t)(b * NN + n0 + n)) * C2 + zoff) + w) = val;
    }
}

// ================================================================ kernel 2
// FUSED energy: grid (3*ESP, 8), x = sp*3 + t so the 3 tiles of a split are
// adjacent CTAs (co-resident, k-synchronized -> L2 serves overlapping reads).
// t=0: diag rows 0..127 | t=1: off-diag (A rows 0..127, B rows 128..255)
// t=2: diag rows 128..255. All tiles cover k [sp*2048, (sp+1)*2048).
extern "C" __global__ void __launch_bounds__(256, 2)
k_energy()
{
    extern __shared__ char smem[];
    u32 sb = smem_u32(smem);
    int tid = threadIdx.x, wid = tid >> 5, lane = tid & 31;
    int b = blockIdx.y;
    int sp = blockIdx.x / 3, t = blockIdx.x % 3;
    const __nv_bfloat16* Xh = g_xcon_hi + (size_t)b * C2 * NN;
    const __nv_bfloat16* Xl = g_xcon_lo + (size_t)b * C2 * NN;
    int k0 = sp * 2048;

    float acc[4][4][4];
    #pragma unroll
    for (int i = 0; i < 4; i++)
        #pragma unroll
        for (int j = 0; j < 4; j++)
            #pragma unroll
            for (int e = 0; e < 4; e++) acc[i][j][e] = 0.f;

    int m0w = (wid >> 2) * 64, n0w = (wid & 3) * 32;
    int r = lane >> 2, cpo = (lane & 3) * 2;
    float* Ep = g_epart + ((size_t)(b * ESP + sp)) * C2 * C2;

    if (t == 1) {
        // off-diag: 64 chunks of K=32, 256-row planes, 2 bufs
        auto issue = [&](int ch, int buf) {
            int kb = k0 + ch * 32;
            for (int it = tid; it < 2048; it += 256) {
                int pl = it >> 10, rr = (it >> 2) & 255, seg = it & 3;
                const __nv_bfloat16* src =
                    (pl ? Xl : Xh) + (size_t)rr * NN + kb + seg * 8;
                CPA16(sb + buf * O_BUF + pl * O_PL + rr * O_ST + seg * 16, src);
            }
            CP_COMMIT();
        };
        issue(0, 0);
        for (int ch = 0; ch < 64; ch++) {
            int buf = ch & 1;
            if (ch + 1 < 64) { issue(ch + 1, (ch + 1) & 1); CP_WAIT1(); }
            else             { CP_WAIT0(); }
            __syncthreads();
            u32 base = buf * O_BUF;
            gemm3_k32(sb, base, base + O_PL,
                      base + 128 * O_ST, base + O_PL + 128 * O_ST,
                      acc, wid, lane);
            __syncthreads();
        }
        #pragma unroll
        for (int mi = 0; mi < 4; mi++) {
            int i = m0w + mi * 16 + r;
            #pragma unroll
            for (int ni = 0; ni < 4; ni++) {
                int j = 128 + n0w + ni * 8 + cpo;
                *(float2*)&Ep[(size_t)i * C2 + j] =
                    make_float2(acc[mi][ni][0], acc[mi][ni][1]);
                *(float2*)&Ep[(size_t)(i + 8) * C2 + j] =
                    make_float2(acc[mi][ni][2], acc[mi][ni][3]);
            }
        }
    } else {
        int i0 = (t == 2) ? 128 : 0;
        // diag Gram: 32 chunks of K=64, 128-row planes, 3-stage pipeline
        auto issue = [&](int ch, int buf) {
            int kb = k0 + ch * 64;
            for (int it = tid; it < 2048; it += 256) {
                int pl = it >> 10, rr = (it >> 3) & 127, seg = it & 7;
                const __nv_bfloat16* src =
                    (pl ? Xl : Xh) + (size_t)(i0 + rr) * NN + kb + seg * 8;
                CPA16(sb + buf * 36864 + pl * E_PL + rr * E_ST + seg * 16, src);
            }
            CP_COMMIT();
        };
        issue(0, 0);
        issue(1, 1);
        for (int ch = 0; ch < 32; ch++) {
            int buf = ch % 3;
            if (ch + 2 < 32) { issue(ch + 2, (ch + 2) % 3); CP_WAIT2(); }
            else if (ch + 1 < 32) { CP_WAIT1(); }
            else { CP_WAIT0(); }
            __syncthreads();
            u32 base = buf * 36864;
            gemm3_k64(sb, base, base + E_PL, base, base + E_PL, acc, wid, lane);
            __syncthreads();
        }
        #pragma unroll
        for (int mi = 0; mi < 4; mi++) {
            int i = i0 + m0w + mi * 16 + r;
            #pragma unroll
            for (int ni = 0; ni < 4; ni++) {
                int j = i0 + n0w + ni * 8 + cpo;
                *(float2*)&Ep[(size_t)i * C2 + j] =
                    make_float2(acc[mi][ni][0], acc[mi][ni][1]);
                *(float2*)&Ep[(size_t)(i + 8) * C2 + j] =
                    make_float2(acc[mi][ni][2], acc[mi][ni][3]);
            }
        }
    }
}

// ================================================================ kernel 2c
// unified 16 splits, unrolled, 4 independent partials
extern "C" __global__ void k_ereduce()
{
    int j = threadIdx.x, i = blockIdx.x, b = blockIdx.y;
    int si = i, sj = j;
    if (i >= 128 && j < 128) { si = j; sj = i; }
    size_t base = ((size_t)(b * ESP) * C2 + si) * C2 + sj;
    const size_t str = (size_t)C2 * C2;
    float s0 = 0.f, s1 = 0.f, s2 = 0.f, s3 = 0.f;
    #pragma unroll
    for (int sp = 0; sp < 16; sp += 4) {
        s0 += g_epart[base + (size_t)(sp + 0) * str];
        s1 += g_epart[base + (size_t)(sp + 1) * str];
        s2 += g_epart[base + (size_t)(sp + 2) * str];
        s3 += g_epart[base + (size_t)(sp + 3) * str];
    }
    g_energy[((size_t)b * C2 + i) * C2 + j] =
        ((s0 + s1) + (s2 + s3)) * (1.0f / 16.0f);
}

// ================================================================ kernel 3a
extern "C" __global__ void __launch_bounds__(256)
k_mlp1(const float* __restrict__ t1w, const float* __restrict__ t1b)
{
    __shared__ float sE[8 * 256];
    __shared__ float sW[256 * 33];
    int b = blockIdx.y, rg = blockIdx.x;
    int tid = threadIdx.x;
    const float* E = g_energy + (size_t)b * C2 * C2 + (size_t)rg * 8 * C2;
    #pragma unroll
    for (int t = 0; t < 8; t++) sE[t * 256 + tid] = E[t * 256 + tid];

    float acc[8];
    #pragma unroll
    for (int i = 0; i < 8; i++) acc[i] = 0.f;

    for (int kt = 0; kt < 8; kt++) {
        __syncthreads();
        for (int it = tid; it < 8192; it += 256) {
            int j = it >> 5, k = it & 31;
            sW[j * 33 + k] = t1w[(size_t)j * C2 + kt * 32 + k];
        }
        __syncthreads();
        #pragma unroll
        for (int k = 0; k < 32; k++) {
            float w = sW[tid * 33 + k];
            #pragma unroll
            for (int i = 0; i < 8; i++)
                acc[i] += sE[i * 256 + kt * 32 + k] * w;
        }
    }
    float bv = t1b[tid];
    float* O = g_e1 + (size_t)b * C2 * C2 + (size_t)rg * 8 * C2;
    #pragma unroll
    for (int i = 0; i < 8; i++)
        O[i * 256 + tid] = fmaxf(acc[i] + bv, 0.f);
}

// ================================================================ kernel 3b
extern "C" __global__ void __launch_bounds__(128)
k_mlp2(const float* __restrict__ t2w, const float* __restrict__ t2b)
{
    __shared__ float sR[8 * 256];
    __shared__ float sW2[128 * 33];
    __shared__ float red[128];
    int b = blockIdx.y, rg = blockIdx.x, j = threadIdx.x;
    const float* E1 = g_e1 + (size_t)b * C2 * C2 + (size_t)rg * 8 * C2;
    for (int it = j; it < 2048; it += 128) sR[it] = E1[it];

    float acc[8];
    #pragma unroll
    for (int i = 0; i < 8; i++) acc[i] = 0.f;

    for (int kt = 0; kt < 8; kt++) {
        __syncthreads();
        for (int it = j; it < 4096; it += 128) {
            int jj = it >> 5, k = it & 31;
            sW2[jj * 33 + k] = t2w[(size_t)jj * C2 + kt * 32 + k];
        }
        __syncthreads();
        #pragma unroll
        for (int k = 0; k < 32; k++) {
            float w = sW2[j * 33 + k];
            #pragma unroll
            for (int i = 0; i < 8; i++)
                acc[i] += sR[i * 256 + kt * 32 + k] * w;
        }
    }
    float bv = t2b[j];
    float v[8];
    #pragma unroll
    for (int i = 0; i < 8; i++) v[i] = fmaxf(acc[i] + bv, 0.f);

    #pragma unroll
    for (int i = 0; i < 8; i++) {
        __syncthreads();
        red[j] = v[i]; __syncthreads();
        for (int s = 64; s > 0; s >>= 1) {
            if (j < s) red[j] = fmaxf(red[j], red[j + s]);
            __syncthreads();
        }
        float m = red[0]; __syncthreads();
        float e = expf(v[i] - m);
        red[j] = e; __syncthreads();
        for (int s = 64; s > 0; s >>= 1) {
            if (j < s) red[j] += red[j + s];
            __syncthreads();
        }
        float sum = red[0];
        g_attnT16[((size_t)(b * CC + j)) * C2 + rg * 8 + i] =
            __float2half_rn(e / sum);
    }
}

// ================================================================ kernel 4
// K=256 as 4 chunks of 64, 3-stage cp.async pipeline, occ 2.
extern "C" __global__ void __launch_bounds__(256, 2)
k_out(float* __restrict__ out)
{
    extern __shared__ char smem[];
    u32 sb = smem_u32(smem);
    int tid = threadIdx.x, wid = tid >> 5, lane = tid & 31;
    int b = blockIdx.y, n0 = blockIdx.x * 128;
    const __half* At = g_attnT16 + (size_t)b * CC * C2;
    const __half* V = g_vcon + (size_t)b * NN * C2;

    float acc[4][4][4];
    #pragma unroll
    for (int i = 0; i < 4; i++)
        #pragma unroll
        for (int j = 0; j < 4; j++)
            #pragma unroll
            for (int e = 0; e < 4; e++) acc[i][j][e] = 0.f;

    auto fill = [&](int ch, int buf) {
        int d0 = ch * 64;
        u32 sbb = sb + buf * 36864;
        for (int it = tid; it < 1024; it += 256) {
            int c = it >> 3, seg = it & 7;
            CPA16(sbb + c * E_ST + seg * 16,
                  At + (size_t)c * C2 + d0 + seg * 8);
        }
        for (int it = tid; it < 1024; it += 256) {
            int n = it >> 3, seg = it & 7;
            CPA16(sbb + E_PL + n * E_ST + seg * 16,
                  V + (size_t)(n0 + n) * C2 + d0 + seg * 8);
        }
        CP_COMMIT();
    };

    fill(0, 0);
    fill(1, 1);
    for (int ch = 0; ch < 4; ch++) {
        int buf = ch % 3;
        if (ch + 2 < 4) { fill(ch + 2, (ch + 2) % 3); CP_WAIT2(); }
        else if (ch + 1 < 4) { CP_WAIT1(); }
        else { CP_WAIT0(); }
        __syncthreads();
        u32 base = buf * 36864;
        gemm1_k64(sb, base, base + E_PL, acc, wid, lane);
        __syncthreads();
    }

    int m0w = (wid >> 2) * 64, n0w = (wid & 3) * 32;
    int r = lane >> 2, cpo = (lane & 3) * 2;
    #pragma unroll
    for (int mi = 0; mi < 4; mi++) {
        int m = m0w + mi * 16 + r;
        #pragma unroll
        for (int ni = 0; ni < 4; ni++) {
            int n = n0w + ni * 8 + cpo;
            *(float2*)&out[((size_t)(b * CC + m)) * NN + n0 + n] =
                make_float2(acc[mi][ni][0], acc[mi][ni][1]);
            *(float2*)&out[((size_t)(b * CC + m + 8)) * NN + n0 + n] =
                make_float2(acc[mi][ni][2], acc[mi][ni][3]);
        }
    }
}

// ---------------------------------------------------------------- launch
extern "C" void kernel_launch(void* const* d_in, const int* in_sizes, int n_in,
                              void* d_out, int out_size)
{
    const float* x   = (const float*)d_in[0];
    const float* y   = (const float*)d_in[1];
    const float* qw  = (const float*)d_in[2];
    const float* qb  = (const float*)d_in[3];
    const float* kw  = (const float*)d_in[4];
    const float* kb  = (const float*)d_in[5];
    const float* v1w = (const float*)d_in[6];
    const float* v1b = (const float*)d_in[7];
    const float* v2w = (const float*)d_in[8];
    const float* v2b = (const float*)d_in[9];
    const float* t1w = (const float*)d_in[10];
    const float* t1b = (const float*)d_in[11];
    const float* t2w = (const float*)d_in[12];
    const float* t2b = (const float*)d_in[13];
    float* out = (float*)d_out;

    cudaFuncSetAttribute(k_pconv_qk, cudaFuncAttributeMaxDynamicSharedMemorySize, 4 * E_PL + 512);
    cudaFuncSetAttribute(k_pconv_v,  cudaFuncAttributeMaxDynamicSharedMemorySize, 2 * E_PL + 512);
    cudaFuncSetAttribute(k_energy,   cudaFuncAttributeMaxDynamicSharedMemorySize, 110592);
    cudaFuncSetAttribute(k_out,      cudaFuncAttributeMaxDynamicSharedMemorySize, 110592);

    k_pconv_qk<<<dim3(NN / 128, BB, 2), 256, 4 * E_PL + 512>>>(x, y, qw, qb, kw, kb);
    k_pconv_v <<<dim3(NN / 128, BB, 2), 256, 2 * E_PL + 512>>>(x, y, v1w, v1b, v2w, v2b);
    k_energy  <<<dim3(3 * ESP, BB), 256, 110592>>>();
    k_ereduce <<<dim3(C2, BB), C2>>>();
    k_mlp1    <<<dim3(32, BB), 256>>>(t1w, t1b);
    k_mlp2    <<<dim3(32, BB), 128>>>(t2w, t2b);
    k_out     <<<dim3(NN / 128, BB), 256, 110592>>>(out);
}